// round 8
// baseline (speedup 1.0000x reference)
#include <cuda_runtime.h>
#include <cuda_bf16.h>
#include <math.h>
#include <stdint.h>

#define B_  2
#define S_  512
#define V_  32000
#define D_  768
#define F_  2048
#define L_  4
#define H_  12
#define HD_ 64
#define FCS_ 8
#define YW_ (S_ + FCS_ - 1)   /* 519 */
#define NT_ (B_ * S_)         /* 1024 rows */

typedef __nv_bfloat16 bf16;

// ---------------- static scratch (allocation-free rule) ----------------
__device__ float  g_h [NT_ * D_];
__device__ float  g_a [NT_ * D_];          // fp32 rmsnorm out (heads)
__device__ float  g_q [NT_ * D_];
__device__ float  g_k [NT_ * D_];
__device__ float  g_v [NT_ * D_];
__device__ float  g_g1[NT_ * F_];
__device__ float  g_c [NT_ * V_];          // context head logits c (131 MB)
__device__ float2 g_rope[S_ * 32];
__device__ double g_acc[4];                // [0]=softplus [1]=delta [2]=nll [3]=valid

// hi/lo bf16 activations
__device__ __align__(16) bf16 g_ah[NT_ * D_], g_al[NT_ * D_];
__device__ __align__(16) bf16 g_oh[NT_ * D_], g_ol[NT_ * D_];
__device__ __align__(16) bf16 g_uh[NT_ * F_], g_ul[NT_ * F_];

// hi/lo bf16 weights (split once per launch)
__device__ __align__(16) bf16 g_wq_h[L_*D_*D_], g_wq_l[L_*D_*D_];
__device__ __align__(16) bf16 g_wk_h[L_*D_*D_], g_wk_l[L_*D_*D_];
__device__ __align__(16) bf16 g_wv_h[L_*D_*D_], g_wv_l[L_*D_*D_];
__device__ __align__(16) bf16 g_wo_h[L_*D_*D_], g_wo_l[L_*D_*D_];
__device__ __align__(16) bf16 g_w1_h[L_*F_*D_], g_w1_l[L_*F_*D_];
__device__ __align__(16) bf16 g_w3_h[L_*F_*D_], g_w3_l[L_*F_*D_];
__device__ __align__(16) bf16 g_w2_h[L_*D_*F_], g_w2_l[L_*D_*F_];

__device__ __forceinline__ float softplusf(float x) {
    if (x > 15.0f) return x;
    return log1pf(expf(x));
}

__device__ __forceinline__ uint32_t f2tf32(float x) {
    uint32_t r; asm("cvt.rna.tf32.f32 %0, %1;" : "=r"(r) : "f"(x)); return r;
}

__device__ __forceinline__ void mma_tf32(float& c0, float& c1, float& c2, float& c3,
                                         uint32_t a0, uint32_t a1, uint32_t a2, uint32_t a3,
                                         uint32_t b0, uint32_t b1) {
    asm volatile("mma.sync.aligned.m16n8k8.row.col.f32.tf32.tf32.f32 "
                 "{%0,%1,%2,%3}, {%4,%5,%6,%7}, {%8,%9}, {%0,%1,%2,%3};"
                 : "+f"(c0), "+f"(c1), "+f"(c2), "+f"(c3)
                 : "r"(a0), "r"(a1), "r"(a2), "r"(a3), "r"(b0), "r"(b1));
}

__device__ __forceinline__ void mma_bf16(float& c0, float& c1, float& c2, float& c3,
                                         uint32_t a0, uint32_t a1, uint32_t a2, uint32_t a3,
                                         uint32_t b0, uint32_t b1) {
    asm volatile("mma.sync.aligned.m16n8k16.row.col.f32.bf16.bf16.f32 "
                 "{%0,%1,%2,%3}, {%4,%5,%6,%7}, {%8,%9}, {%0,%1,%2,%3};"
                 : "+f"(c0), "+f"(c1), "+f"(c2), "+f"(c3)
                 : "r"(a0), "r"(a1), "r"(a2), "r"(a3), "r"(b0), "r"(b1));
}

__global__ void zero_acc_kernel() {
    if (threadIdx.x < 4) g_acc[threadIdx.x] = 0.0;
}

// ---------------- hi/lo split (elementwise, float4 vectorized) ----------------
__global__ void split4_kernel(const float* __restrict__ src,
                              bf16* __restrict__ hi, bf16* __restrict__ lo, int n4) {
    int i = blockIdx.x * blockDim.x + threadIdx.x;
    if (i >= n4) return;
    float4 v = ((const float4*)src)[i];
    __nv_bfloat162 h01 = __floats2bfloat162_rn(v.x, v.y);
    __nv_bfloat162 h23 = __floats2bfloat162_rn(v.z, v.w);
    __nv_bfloat162 l01 = __floats2bfloat162_rn(v.x - __bfloat162float(h01.x),
                                               v.y - __bfloat162float(h01.y));
    __nv_bfloat162 l23 = __floats2bfloat162_rn(v.z - __bfloat162float(h23.x),
                                               v.w - __bfloat162float(h23.y));
    ((__nv_bfloat162*)hi)[2 * i]     = h01;
    ((__nv_bfloat162*)hi)[2 * i + 1] = h23;
    ((__nv_bfloat162*)lo)[2 * i]     = l01;
    ((__nv_bfloat162*)lo)[2 * i + 1] = l23;
}

// ---------------- embedding gather ----------------
__global__ void embed_kernel(const int* __restrict__ x, const float* __restrict__ emb) {
    int i = blockIdx.x * blockDim.x + threadIdx.x;
    if (i >= NT_ * D_) return;
    int row = i / D_;
    int d   = i - row * D_;
    g_h[i] = emb[(size_t)x[row] * D_ + d];
}

// ---------------- rmsnorm (SPLIT=1: write bf16 hi/lo; else fp32) ----------------
template<int SPLIT>
__global__ void rmsnorm_kernel(const float* __restrict__ in, const float* __restrict__ w,
                               float* __restrict__ out, bf16* __restrict__ oh,
                               bf16* __restrict__ ol) {
    int row = blockIdx.x;
    const float* ip = in + row * D_;
    __shared__ float red[256];
    float ss = 0.f;
    for (int d = threadIdx.x; d < D_; d += 256) { float v = ip[d]; ss += v * v; }
    red[threadIdx.x] = ss; __syncthreads();
    for (int st = 128; st > 0; st >>= 1) {
        if (threadIdx.x < st) red[threadIdx.x] += red[threadIdx.x + st];
        __syncthreads();
    }
    float rs = rsqrtf(red[0] / (float)D_ + 1e-5f);
    for (int d = threadIdx.x; d < D_; d += 256) {
        float v = ip[d] * rs * w[d];
        if (SPLIT) {
            bf16 h = __float2bfloat16_rn(v);
            oh[row * D_ + d] = h;
            ol[row * D_ + d] = __float2bfloat16_rn(v - __bfloat162float(h));
        } else {
            out[row * D_ + d] = v;
        }
    }
}

#define TLD 20   /* smem row stride (u32): fragment loads conflict-free */

// =======================================================================
//  tf32 tensor-core NT-GEMM (head projections; validated, unchanged)
//  EPI: 0=store 4=store+softplus-sum
// =======================================================================
template<int BM, int BN, int WM, int WN, int EPI>
__global__ __launch_bounds__(WM * WN * 32)
void gemm_tc(const float* __restrict__ A, const float* __restrict__ Bw,
             float* __restrict__ C, int N, int K) {
    constexpr int THREADS = WM * WN * 32;
    constexpr int WTM = BM / WM;
    constexpr int WTN = BN / WN;
    constexpr int MT  = WTM / 16;
    constexpr int NTT = WTN / 8;
    constexpr int RPP = THREADS / 2;
    constexpr int NLA = BM / RPP;
    constexpr int NLB = BN / RPP;

    __shared__ uint32_t As[2][BM][TLD];
    __shared__ uint32_t Bs[2][BN][TLD];
    __shared__ float sred[THREADS];

    const int tid  = threadIdx.x;
    const int lane = tid & 31;
    const int wid  = tid >> 5;
    const int wm   = wid / WN;
    const int wn   = wid % WN;
    const int bm   = blockIdx.x * BM;
    const int bn   = blockIdx.y * BN;

    const int lr = tid >> 1;
    const int ks = (tid & 1) * 8;
    const float* Ag = A  + (size_t)(bm + lr) * K + ks;
    const float* Bg = Bw + (size_t)(bn + lr) * K + ks;

    float acc[MT][NTT][4];
#pragma unroll
    for (int i = 0; i < MT; i++)
#pragma unroll
        for (int j = 0; j < NTT; j++)
#pragma unroll
            for (int q = 0; q < 4; q++) acc[i][j][q] = 0.f;

    float4 pa[NLA][2], pb[NLB][2];

#pragma unroll
    for (int l = 0; l < NLA; l++) {
        pa[l][0] = *(const float4*)(Ag + (size_t)l * RPP * K);
        pa[l][1] = *(const float4*)(Ag + (size_t)l * RPP * K + 4);
    }
#pragma unroll
    for (int l = 0; l < NLB; l++) {
        pb[l][0] = *(const float4*)(Bg + (size_t)l * RPP * K);
        pb[l][1] = *(const float4*)(Bg + (size_t)l * RPP * K + 4);
    }

    auto store_tiles = [&](int buf) {
#pragma unroll
        for (int l = 0; l < NLA; l++) {
            uint4 u0 = make_uint4(f2tf32(pa[l][0].x), f2tf32(pa[l][0].y),
                                  f2tf32(pa[l][0].z), f2tf32(pa[l][0].w));
            uint4 u1 = make_uint4(f2tf32(pa[l][1].x), f2tf32(pa[l][1].y),
                                  f2tf32(pa[l][1].z), f2tf32(pa[l][1].w));
            *(uint4*)&As[buf][lr + l * RPP][ks]     = u0;
            *(uint4*)&As[buf][lr + l * RPP][ks + 4] = u1;
        }
#pragma unroll
        for (int l = 0; l < NLB; l++) {
            uint4 u0 = make_uint4(f2tf32(pb[l][0].x), f2tf32(pb[l][0].y),
                                  f2tf32(pb[l][0].z), f2tf32(pb[l][0].w));
            uint4 u1 = make_uint4(f2tf32(pb[l][1].x), f2tf32(pb[l][1].y),
                                  f2tf32(pb[l][1].z), f2tf32(pb[l][1].w));
            *(uint4*)&Bs[buf][lr + l * RPP][ks]     = u0;
            *(uint4*)&Bs[buf][lr + l * RPP][ks + 4] = u1;
        }
    };

    store_tiles(0);
    __syncthreads();

    const int nk = K / 16;
    for (int kc = 0; kc < nk; kc++) {
        const int cur = kc & 1;
        if (kc + 1 < nk) {
            const float* Ap = Ag + (kc + 1) * 16;
            const float* Bp = Bg + (kc + 1) * 16;
#pragma unroll
            for (int l = 0; l < NLA; l++) {
                pa[l][0] = *(const float4*)(Ap + (size_t)l * RPP * K);
                pa[l][1] = *(const float4*)(Ap + (size_t)l * RPP * K + 4);
            }
#pragma unroll
            for (int l = 0; l < NLB; l++) {
                pb[l][0] = *(const float4*)(Bp + (size_t)l * RPP * K);
                pb[l][1] = *(const float4*)(Bp + (size_t)l * RPP * K + 4);
            }
        }

#pragma unroll
        for (int kk = 0; kk < 2; kk++) {
            const int kq = kk * 8 + (lane & 3);
            uint32_t af[MT][4], bf[NTT][2];
#pragma unroll
            for (int mt = 0; mt < MT; mt++) {
                int row = wm * WTM + mt * 16 + (lane >> 2);
                af[mt][0] = As[cur][row][kq];
                af[mt][1] = As[cur][row + 8][kq];
                af[mt][2] = As[cur][row][kq + 4];
                af[mt][3] = As[cur][row + 8][kq + 4];
            }
#pragma unroll
            for (int nt = 0; nt < NTT; nt++) {
                int nr = wn * WTN + nt * 8 + (lane >> 2);
                bf[nt][0] = Bs[cur][nr][kq];
                bf[nt][1] = Bs[cur][nr][kq + 4];
            }
#pragma unroll
            for (int mt = 0; mt < MT; mt++)
#pragma unroll
                for (int nt = 0; nt < NTT; nt++)
                    mma_tf32(acc[mt][nt][0], acc[mt][nt][1],
                             acc[mt][nt][2], acc[mt][nt][3],
                             af[mt][0], af[mt][1], af[mt][2], af[mt][3],
                             bf[nt][0], bf[nt][1]);
        }

        if (kc + 1 < nk) store_tiles(cur ^ 1);
        __syncthreads();
    }

    float spsum = 0.f;
#pragma unroll
    for (int mt = 0; mt < MT; mt++) {
        int row = bm + wm * WTM + mt * 16 + (lane >> 2);
#pragma unroll
        for (int nt = 0; nt < NTT; nt++) {
            int col = bn + wn * WTN + nt * 8 + (lane & 3) * 2;
            float* a4 = acc[mt][nt];
            size_t i0 = (size_t)row * N + col;
            size_t i1 = (size_t)(row + 8) * N + col;
            if (EPI == 4) {
                spsum += softplusf(a4[0]) + softplusf(a4[1]) +
                         softplusf(a4[2]) + softplusf(a4[3]);
            }
            *(float2*)(C + i0) = make_float2(a4[0], a4[1]);
            *(float2*)(C + i1) = make_float2(a4[2], a4[3]);
        }
    }
    if (EPI == 4) {
        sred[tid] = spsum; __syncthreads();
        for (int st = THREADS / 2; st > 0; st >>= 1) {
            if (tid < st) sred[tid] += sred[tid + st];
            __syncthreads();
        }
        if (tid == 0) atomicAdd(&g_acc[0], (double)sred[0]);
    }
}

// =======================================================================
//  Pre-split bf16 hi/lo NT-GEMM:  C[m,n] (op)= sum_k A[m,k]*W[n,k]
//  Operands already decomposed (hi,lo bf16 arrays).  3x m16n8k16 per k16,
//  zero conversions in mainloop.  EPI: 0=store 1=add 2=silu 3=mulG->hi/lo
// =======================================================================
template<int BM, int BN, int WM, int WN, int EPI>
__device__ __forceinline__ void gemm_bf2_core(const bf16* __restrict__ Ah,
                                              const bf16* __restrict__ Al,
                                              const bf16* __restrict__ Bh,
                                              const bf16* __restrict__ Bl,
                                              float* __restrict__ C,
                                              const float* __restrict__ G,
                                              bf16* __restrict__ Oh,
                                              bf16* __restrict__ Ol,
                                              int N, int K, int bm, int bn) {
    constexpr int THREADS = WM * WN * 32;
    constexpr int WTM = BM / WM;
    constexpr int WTN = BN / WN;
    constexpr int MT  = WTM / 16;
    constexpr int NTT = WTN / 8;
    constexpr int RPP = THREADS / 2;
    constexpr int NLA = BM / RPP;
    constexpr int NLB = BN / RPP;

    __shared__ uint32_t As[2][BM][TLD];
    __shared__ uint32_t Bs[2][BN][TLD];

    const int tid  = threadIdx.x;
    const int lane = tid & 31;
    const int wid  = tid >> 5;
    const int wm   = wid / WN;
    const int wn   = wid % WN;

    const int lr = tid >> 1;
    const int ks = (tid & 1) * 8;   // element offset 0/8 in k16 chunk
    const int js = ks >> 1;         // u32 pair offset 0/4
    const bf16* Agh = Ah + (size_t)(bm + lr) * K + ks;
    const bf16* Agl = Al + (size_t)(bm + lr) * K + ks;
    const bf16* Bgh = Bh + (size_t)(bn + lr) * K + ks;
    const bf16* Bgl = Bl + (size_t)(bn + lr) * K + ks;

    float acc[MT][NTT][4];
#pragma unroll
    for (int i = 0; i < MT; i++)
#pragma unroll
        for (int j = 0; j < NTT; j++)
#pragma unroll
            for (int q = 0; q < 4; q++) acc[i][j][q] = 0.f;

    uint4 pah[NLA], pal[NLA], pbh[NLB], pbl[NLB];

#pragma unroll
    for (int l = 0; l < NLA; l++) {
        pah[l] = *(const uint4*)(Agh + (size_t)l * RPP * K);
        pal[l] = *(const uint4*)(Agl + (size_t)l * RPP * K);
    }
#pragma unroll
    for (int l = 0; l < NLB; l++) {
        pbh[l] = *(const uint4*)(Bgh + (size_t)l * RPP * K);
        pbl[l] = *(const uint4*)(Bgl + (size_t)l * RPP * K);
    }

    auto store_tiles = [&](int buf) {
#pragma unroll
        for (int l = 0; l < NLA; l++) {
            *(uint4*)&As[buf][lr + l * RPP][js]     = pah[l];
            *(uint4*)&As[buf][lr + l * RPP][8 + js] = pal[l];
        }
#pragma unroll
        for (int l = 0; l < NLB; l++) {
            *(uint4*)&Bs[buf][lr + l * RPP][js]     = pbh[l];
            *(uint4*)&Bs[buf][lr + l * RPP][8 + js] = pbl[l];
        }
    };

    store_tiles(0);
    __syncthreads();

    const int nk = K / 16;
    for (int kc = 0; kc < nk; kc++) {
        const int cur = kc & 1;
        if (kc + 1 < nk) {
            const int off = (kc + 1) * 16;
#pragma unroll
            for (int l = 0; l < NLA; l++) {
                pah[l] = *(const uint4*)(Agh + (size_t)l * RPP * K + off);
                pal[l] = *(const uint4*)(Agl + (size_t)l * RPP * K + off);
            }
#pragma unroll
            for (int l = 0; l < NLB; l++) {
                pbh[l] = *(const uint4*)(Bgh + (size_t)l * RPP * K + off);
                pbl[l] = *(const uint4*)(Bgl + (size_t)l * RPP * K + off);
            }
        }

        {
            const int jq = lane & 3;
            uint32_t ah[MT][4], al[MT][4], bh[NTT][2], bl[NTT][2];
#pragma unroll
            for (int mt = 0; mt < MT; mt++) {
                int row = wm * WTM + mt * 16 + (lane >> 2);
                ah[mt][0] = As[cur][row][jq];
                ah[mt][1] = As[cur][row + 8][jq];
                ah[mt][2] = As[cur][row][jq + 4];
                ah[mt][3] = As[cur][row + 8][jq + 4];
                al[mt][0] = As[cur][row][jq + 8];
                al[mt][1] = As[cur][row + 8][jq + 8];
                al[mt][2] = As[cur][row][jq + 12];
                al[mt][3] = As[cur][row + 8][jq + 12];
            }
#pragma unroll
            for (int nt = 0; nt < NTT; nt++) {
                int nr = wn * WTN + nt * 8 + (lane >> 2);
                bh[nt][0] = Bs[cur][nr][jq];
                bh[nt][1] = Bs[cur][nr][jq + 4];
                bl[nt][0] = Bs[cur][nr][jq + 8];
                bl[nt][1] = Bs[cur][nr][jq + 12];
            }
#pragma unroll
            for (int mt = 0; mt < MT; mt++)
#pragma unroll
                for (int nt = 0; nt < NTT; nt++) {
                    mma_bf16(acc[mt][nt][0], acc[mt][nt][1], acc[mt][nt][2], acc[mt][nt][3],
                             ah[mt][0], ah[mt][1], ah[mt][2], ah[mt][3],
                             bh[nt][0], bh[nt][1]);
                    mma_bf16(acc[mt][nt][0], acc[mt][nt][1], acc[mt][nt][2], acc[mt][nt][3],
                             ah[mt][0], ah[mt][1], ah[mt][2], ah[mt][3],
                             bl[nt][0], bl[nt][1]);
                    mma_bf16(acc[mt][nt][0], acc[mt][nt][1], acc[mt][nt][2], acc[mt][nt][3],
                             al[mt][0], al[mt][1], al[mt][2], al[mt][3],
                             bh[nt][0], bh[nt][1]);
                }
        }

        if (kc + 1 < nk) store_tiles(cur ^ 1);
        __syncthreads();
    }

    // ---------------- epilogue ----------------
#pragma unroll
    for (int mt = 0; mt < MT; mt++) {
        int row = bm + wm * WTM + mt * 16 + (lane >> 2);
#pragma unroll
        for (int nt = 0; nt < NTT; nt++) {
            int col = bn + wn * WTN + nt * 8 + (lane & 3) * 2;
            float* a4 = acc[mt][nt];
            size_t i0 = (size_t)row * N + col;
            size_t i1 = (size_t)(row + 8) * N + col;
            float2 r0 = make_float2(a4[0], a4[1]);
            float2 r1 = make_float2(a4[2], a4[3]);
            if (EPI == 1) {
                float2 o0 = *(const float2*)(C + i0);
                float2 o1 = *(const float2*)(C + i1);
                r0.x += o0.x; r0.y += o0.y;
                r1.x += o1.x; r1.y += o1.y;
            } else if (EPI == 2) {
                r0.x = r0.x / (1.f + expf(-r0.x));
                r0.y = r0.y / (1.f + expf(-r0.y));
                r1.x = r1.x / (1.f + expf(-r1.x));
                r1.y = r1.y / (1.f + expf(-r1.y));
            } else if (EPI == 3) {
                float2 g0 = *(const float2*)(G + i0);
                float2 g1v = *(const float2*)(G + i1);
                r0.x *= g0.x; r0.y *= g0.y;
                r1.x *= g1v.x; r1.y *= g1v.y;
            }
            if (EPI == 3) {
                __nv_bfloat162 h0 = __floats2bfloat162_rn(r0.x, r0.y);
                __nv_bfloat162 h1 = __floats2bfloat162_rn(r1.x, r1.y);
                __nv_bfloat162 l0 = __floats2bfloat162_rn(r0.x - __bfloat162float(h0.x),
                                                          r0.y - __bfloat162float(h0.y));
                __nv_bfloat162 l1 = __floats2bfloat162_rn(r1.x - __bfloat162float(h1.x),
                                                          r1.y - __bfloat162float(h1.y));
                *(__nv_bfloat162*)(Oh + i0) = h0;
                *(__nv_bfloat162*)(Oh + i1) = h1;
                *(__nv_bfloat162*)(Ol + i0) = l0;
                *(__nv_bfloat162*)(Ol + i1) = l1;
            } else {
                *(float2*)(C + i0) = r0;
                *(float2*)(C + i1) = r1;
            }
        }
    }
}

template<int BM, int BN, int WM, int WN, int EPI>
__global__ __launch_bounds__(WM * WN * 32)
void gemm_bf2(const bf16* __restrict__ Ah, const bf16* __restrict__ Al,
              const bf16* __restrict__ Bh, const bf16* __restrict__ Bl,
              float* __restrict__ C, const float* __restrict__ G,
              bf16* __restrict__ Oh, bf16* __restrict__ Ol, int N, int K) {
    gemm_bf2_core<BM, BN, WM, WN, EPI>(Ah, Al, Bh, Bl, C, G, Oh, Ol, N, K,
                                       blockIdx.x * BM, blockIdx.y * BN);
}

// fused q/k/v (blockIdx.z selects weight/output), layer weights via offset
__global__ __launch_bounds__(128)
void gemm_qkv_bf2(const bf16* __restrict__ Ah, const bf16* __restrict__ Al,
                  int layer_off,
                  float* __restrict__ C0, float* __restrict__ C1, float* __restrict__ C2,
                  int N, int K) {
    const bf16* Bzh; const bf16* Bzl; float* Cz;
    if (blockIdx.z == 0)      { Bzh = g_wq_h + layer_off; Bzl = g_wq_l + layer_off; Cz = C0; }
    else if (blockIdx.z == 1) { Bzh = g_wk_h + layer_off; Bzl = g_wk_l + layer_off; Cz = C1; }
    else                      { Bzh = g_wv_h + layer_off; Bzl = g_wv_l + layer_off; Cz = C2; }
    gemm_bf2_core<64, 64, 2, 2, 0>(Ah, Al, Bzh, Bzl, Cz, nullptr, nullptr, nullptr,
                                   N, K, blockIdx.x * 64, blockIdx.y * 64);
}

// ---------------- RoPE ----------------
__global__ void rope_table_kernel() {
    int i = blockIdx.x * blockDim.x + threadIdx.x;
    if (i >= S_ * 32) return;
    int s = i / 32, p = i - (i / 32) * 32;
    float f   = expf((float)(2 * p) * (-logf(10000.0f) / (float)HD_));
    float ang = (float)s * f;
    double a  = (double)ang;
    g_rope[i] = make_float2((float)cos(a), (float)sin(a));
}

__global__ void rope_apply_kernel() {
    int idx = blockIdx.x * blockDim.x + threadIdx.x;          // over B*S*H*32
    if (idx >= B_ * S_ * H_ * 32) return;
    int p = idx & 31;
    int h = (idx >> 5) % H_;
    int s = (idx / (32 * H_)) % S_;
    int b = idx / (32 * H_ * S_);
    float2 cs = g_rope[s * 32 + p];
    int base = ((b * S_ + s) * D_) + h * HD_ + 2 * p;
    float xr, xi;
    xr = g_q[base]; xi = g_q[base + 1];
    g_q[base]     = xr * cs.x - xi * cs.y;
    g_q[base + 1] = xr * cs.y + xi * cs.x;
    xr = g_k[base]; xi = g_k[base + 1];
    g_k[base]     = xr * cs.x - xi * cs.y;
    g_k[base + 1] = xr * cs.y + xi * cs.x;
}

// ---------------- flash-style attention (writes o hi/lo) ----------------
__global__ __launch_bounds__(256)
void attn_flash() {
    const int qt = blockIdx.x;
    const int bh = blockIdx.y;
    const int b = bh / H_, h = bh - (bh / H_) * H_;
    const int tid = threadIdx.x;
    const int q  = tid >> 2;
    const int dg = (tid & 3) * 16;
    const int q0 = qt * 64;

    __shared__ float KS[64][68];
    __shared__ float Vs[64][68];
    __shared__ float rowm[64], rows[64], cfs[64];

    float4 qr[16];
    const float* qp = g_q + ((size_t)(b * S_ + q0 + q)) * D_ + h * HD_;
#pragma unroll
    for (int j = 0; j < 16; j++) qr[j] = *(const float4*)(qp + 4 * j);

    float acc[16];
#pragma unroll
    for (int j = 0; j < 16; j++) acc[j] = 0.f;
    if (tid < 64) { rowm[tid] = -1e30f; rows[tid] = 0.f; }

    for (int k0 = 0; k0 <= q0; k0 += 64) {
        {
            int r = tid >> 2, c = (tid & 3) * 16;
            const float* kp = g_k + ((size_t)(b * S_ + k0 + r)) * D_ + h * HD_ + c;
            const float* vp = g_v + ((size_t)(b * S_ + k0 + r)) * D_ + h * HD_ + c;
#pragma unroll
            for (int j = 0; j < 4; j++) {
                *(float4*)&KS[r][c + 4 * j] = *(const float4*)(kp + 4 * j);
                *(float4*)&Vs[r][c + 4 * j] = *(const float4*)(vp + 4 * j);
            }
        }
        __syncthreads();

        float sreg[16];
        {
            const int kb = (tid & 3) * 16;
#pragma unroll
            for (int j = 0; j < 16; j++) {
                int kk = kb + j;
                float d = 0.f;
#pragma unroll
                for (int t4 = 0; t4 < 16; t4++) {
                    float4 kv = *(const float4*)&KS[kk][4 * t4];
                    d += qr[t4].x * kv.x + qr[t4].y * kv.y +
                         qr[t4].z * kv.z + qr[t4].w * kv.w;
                }
                sreg[j] = (k0 + kk <= q0 + q) ? d * 0.125f : -1e30f;
            }
        }
        __syncthreads();

        {
            const int kb = (tid & 3) * 16;
#pragma unroll
            for (int j = 0; j < 16; j++) KS[q][kb + j] = sreg[j];
        }
        __syncthreads();

        if (tid < 64) {
            float mo = rowm[tid];
            float tm = mo;
#pragma unroll 8
            for (int kk = 0; kk < 64; kk++) tm = fmaxf(tm, KS[tid][kk]);
            float cf = expf(mo - tm);
            float ps = 0.f;
#pragma unroll 8
            for (int kk = 0; kk < 64; kk++) {
                float p = expf(KS[tid][kk] - tm);
                KS[tid][kk] = p;
                ps += p;
            }
            rowm[tid] = tm;
            rows[tid] = rows[tid] * cf + ps;
            cfs[tid] = cf;
        }
        __syncthreads();

        {
            float cf = cfs[q];
#pragma unroll
            for (int j = 0; j < 16; j++) acc[j] *= cf;
            for (int kk = 0; kk < 64; kk++) {
                float p = KS[q][kk];
#pragma unroll
                for (int j4 = 0; j4 < 4; j4++) {
                    float4 vv = *(const float4*)&Vs[kk][dg + 4 * j4];
                    acc[4 * j4 + 0] += p * vv.x;
                    acc[4 * j4 + 1] += p * vv.y;
                    acc[4 * j4 + 2] += p * vv.z;
                    acc[4 * j4 + 3] += p * vv.w;
                }
            }
        }
        __syncthreads();
    }

    float inv = 1.f / rows[q];
    size_t base = ((size_t)(b * S_ + q0 + q)) * D_ + h * HD_ + dg;
#pragma unroll
    for (int j2 = 0; j2 < 8; j2++) {
        float v0 = acc[2 * j2] * inv, v1 = acc[2 * j2 + 1] * inv;
        __nv_bfloat162 hh = __floats2bfloat162_rn(v0, v1);
        __nv_bfloat162 ll = __floats2bfloat162_rn(v0 - __bfloat162float(hh.x),
                                                  v1 - __bfloat162float(hh.y));
        *(__nv_bfloat162*)(g_oh + base + 2 * j2) = hh;
        *(__nv_bfloat162*)(g_ol + base + 2 * j2) = ll;
    }
}

// ---------------- sparse BCE correction ----------------
__global__ void corr_kernel(const int* __restrict__ y) {
    int s = blockIdx.x * blockDim.x + threadIdx.x;
    if (s >= S_) return;
    int tok[2][FCS_];
    for (int b = 0; b < 2; b++)
        for (int j = 0; j < FCS_; j++)
            tok[b][j] = y[b * YW_ + (FCS_ - 1) + ((s - (FCS_ - 1) + j + S_) & (S_ - 1))];
    double dsum = 0.0;
    for (int b = 0; b < 2; b++)
        for (int j = 0; j < FCS_; j++) {
            int v = tok[b][j];
            bool first = true;
            for (int b2 = 0; b2 <= b && first; b2++) {
                int jmax = (b2 == b) ? j : FCS_;
                for (int j2 = 0; j2 < jmax; j2++)
                    if (tok[b2][j2] == v) { first = false; break; }
            }
            if (!first) continue;
            int c0 = 0, c1 = 0;
            for (int j2 = 0; j2 < FCS_; j2++) {
                c0 += (tok[0][j2] == v);
                c1 += (tok[1][j2] == v);
            }
            float w = (c0 > 1 || c1 > 1) ? 1.5f : 1.0f;
            for (int b2 = 0; b2 < 2; b2++) {
                float cv = g_c[((size_t)(b2 * S_ + s)) * V_ + v];
                float t  = ((b2 == 0 ? c0 : c1) > 0) ? 1.f : 0.f;
                dsum += (double)((w - 1.f) * softplusf(cv) - w * t * cv);
            }
        }
    atomicAdd(&g_acc[1], dsum);
}

// ---------------- logits += exp-kernel context (ring-buffer window) ----
#define CTX_CHUNK 128
__global__ void ctx_scan_kernel(float* __restrict__ logits, const float* __restrict__ conv_w) {
    int v = blockIdx.x * blockDim.x + threadIdx.x;
    if (v >= V_) return;
    int b  = blockIdx.y;
    int s0 = blockIdx.z * CTX_CHUNK;
    float e = expf(-conv_w[0]);

    float pw[FCS_];
    pw[FCS_ - 1] = 1.f;
#pragma unroll
    for (int d = FCS_ - 1; d >= 1; --d) pw[d - 1] = pw[d] * e;

    float ring[FCS_];
#pragma unroll
    for (int j = 1; j <= FCS_; j++) {
        int sp = s0 - j;
        ring[(8 - j) & 7] = (sp >= 0) ? g_c[((size_t)(b * S_ + sp)) * V_ + v] : 0.f;
    }

    for (int t = 0; t < CTX_CHUNK / 8; t++) {
#pragma unroll
        for (int u = 0; u < 8; u++) {
            int s = s0 + 8 * t + u;
            size_t idx = ((size_t)(b * S_ + s)) * V_ + v;
            float ctx = 0.f;
#pragma unroll
            for (int d = 1; d <= FCS_; d++)
                ctx += pw[d - 1] * ring[(u - d) & 7];
            logits[idx] += ctx;
            ring[u] = g_c[idx];
        }
    }
}

// ---------------- NLL ----------------
__global__ void nll_kernel(const float* __restrict__ logits, const int* __restrict__ y) {
    int row = blockIdx.x;
    int b = row / S_, s = row - (row / S_) * S_;
    const float* lp = logits + (size_t)row * V_;
    __shared__ float red[256];
    float m = -1e30f;
    for (int v = threadIdx.x; v < V_; v += 256) m = fmaxf(m, lp[v]);
    red[threadIdx.x] = m; __syncthreads();
    for (int st = 128; st > 0; st >>= 1) {
        if (threadIdx.x < st) red[threadIdx.x] = fmaxf(red[threadIdx.x], red[threadIdx.x + st]);
        __syncthreads();
    }
    m = red[0];
    __syncthreads();
    float ssum = 0.f;
    for (int v = threadIdx.x; v < V_; v += 256) ssum += expf(lp[v] - m);
    red[threadIdx.x] = ssum; __syncthreads();
    for (int st = 128; st > 0; st >>= 1) {
        if (threadIdx.x < st) red[threadIdx.x] += red[threadIdx.x + st];
        __syncthreads();
    }
    if (threadIdx.x == 0) {
        int yt = y[b * YW_ + s];
        if (yt != -1) {
            float lse = m + logf(red[0]);
            atomicAdd(&g_acc[2], (double)(lse - lp[yt]));
            atomicAdd(&g_acc[3], 1.0);
        }
    }
}

__global__ void finalize_kernel(float* __restrict__ out) {
    double cnt = g_acc[3] < 1.0 ? 1.0 : g_acc[3];
    out[(size_t)NT_ * V_]     = (float)(g_acc[2] / cnt);
    out[(size_t)NT_ * V_ + 1] = (float)((g_acc[0] + g_acc[1]) / ((double)NT_ * (double)V_));
}

// ---------------- launcher ----------------
extern "C" void kernel_launch(void* const* d_in, const int* in_sizes, int n_in,
                              void* d_out, int out_size) {
    const int*   x      = (const int*)  d_in[0];
    const int*   y      = (const int*)  d_in[1];
    const float* emb    = (const float*)d_in[2];
    const float* wq     = (const float*)d_in[3];
    const float* wk     = (const float*)d_in[4];
    const float* wv     = (const float*)d_in[5];
    const float* wo     = (const float*)d_in[6];
    const float* w1     = (const float*)d_in[7];
    const float* w2     = (const float*)d_in[8];
    const float* w3     = (const float*)d_in[9];
    const float* attn_n = (const float*)d_in[10];
    const float* ffn_n  = (const float*)d_in[11];
    const float* out_n  = (const float*)d_in[12];
    const float* w_out  = (const float*)d_in[13];
    const float* w_ctx  = (const float*)d_in[14];
    const float* conv_w = (const float*)d_in[15];
    float* out = (float*)d_out;

    float *h_, *a_, *q_, *k_, *v_, *g1_, *c_;
    bf16 *ah_, *al_, *oh_, *ol_, *uh_, *ul_;
    bf16 *wqh_, *wql_, *wkh_, *wkl_, *wvh_, *wvl_, *woh_, *wol_;
    bf16 *w1h_, *w1l_, *w3h_, *w3l_, *w2h_, *w2l_;
    cudaGetSymbolAddress((void**)&h_,  g_h);
    cudaGetSymbolAddress((void**)&a_,  g_a);
    cudaGetSymbolAddress((void**)&q_,  g_q);
    cudaGetSymbolAddress((void**)&k_,  g_k);
    cudaGetSymbolAddress((void**)&v_,  g_v);
    cudaGetSymbolAddress((void**)&g1_, g_g1);
    cudaGetSymbolAddress((void**)&c_,  g_c);
    cudaGetSymbolAddress((void**)&ah_, g_ah);
    cudaGetSymbolAddress((void**)&al_, g_al);
    cudaGetSymbolAddress((void**)&oh_, g_oh);
    cudaGetSymbolAddress((void**)&ol_, g_ol);
    cudaGetSymbolAddress((void**)&uh_, g_uh);
    cudaGetSymbolAddress((void**)&ul_, g_ul);
    cudaGetSymbolAddress((void**)&wqh_, g_wq_h); cudaGetSymbolAddress((void**)&wql_, g_wq_l);
    cudaGetSymbolAddress((void**)&wkh_, g_wk_h); cudaGetSymbolAddress((void**)&wkl_, g_wk_l);
    cudaGetSymbolAddress((void**)&wvh_, g_wv_h); cudaGetSymbolAddress((void**)&wvl_, g_wv_l);
    cudaGetSymbolAddress((void**)&woh_, g_wo_h); cudaGetSymbolAddress((void**)&wol_, g_wo_l);
    cudaGetSymbolAddress((void**)&w1h_, g_w1_h); cudaGetSymbolAddress((void**)&w1l_, g_w1_l);
    cudaGetSymbolAddress((void**)&w3h_, g_w3_h); cudaGetSymbolAddress((void**)&w3l_, g_w3_l);
    cudaGetSymbolAddress((void**)&w2h_, g_w2_h); cudaGetSymbolAddress((void**)&w2l_, g_w2_l);

    zero_acc_kernel<<<1, 32>>>();
    embed_kernel<<<(NT_ * D_ + 255) / 256, 256>>>(x, emb);
    rope_table_kernel<<<(S_ * 32 + 255) / 256, 256>>>();

    // weight hi/lo splits (whole tensors, all layers contiguous)
    {
        int nDD4 = L_ * D_ * D_ / 4;
        int nFD4 = L_ * F_ * D_ / 4;
        split4_kernel<<<(nDD4 + 255) / 256, 256>>>(wq, wqh_, wql_, nDD4);
        split4_kernel<<<(nDD4 + 255) / 256, 256>>>(wk, wkh_, wkl_, nDD4);
        split4_kernel<<<(nDD4 + 255) / 256, 256>>>(wv, wvh_, wvl_, nDD4);
        split4_kernel<<<(nDD4 + 255) / 256, 256>>>(wo, woh_, wol_, nDD4);
        split4_kernel<<<(nFD4 + 255) / 256, 256>>>(w1, w1h_, w1l_, nFD4);
        split4_kernel<<<(nFD4 + 255) / 256, 256>>>(w3, w3h_, w3l_, nFD4);
        split4_kernel<<<(nFD4 + 255) / 256, 256>>>(w2, w2h_, w2l_, nFD4);
    }

    dim3 gQKV(NT_ / 64, D_ / 64, 3);     // 16 x 12 x 3 (64x64 tiles)
    dim3 gDs (NT_ / 64, D_ / 64);        // 16 x 12
    dim3 gF  (NT_ / 128, F_ / 64);       // 8 x 32 (128x64 tiles)
    dim3 gTF (NT_ / 128, V_ / 128);      // 8 x 250 (m fast for L2 weight reuse)

    for (int i = 0; i < L_; i++) {
        int offDD = i * D_ * D_;
        int offFD = i * F_ * D_;

        rmsnorm_kernel<1><<<NT_, 256>>>(h_, attn_n + i * D_, nullptr, ah_, al_);
        gemm_qkv_bf2<<<gQKV, 128>>>(ah_, al_, offDD, q_, k_, v_, D_, D_);
        rope_apply_kernel<<<(B_ * S_ * H_ * 32 + 255) / 256, 256>>>();
        attn_flash<<<dim3(S_ / 64, B_ * H_), 256>>>();
        gemm_bf2<64, 64, 2, 2, 1><<<gDs, 128>>>(oh_, ol_, woh_ + offDD, wol_ + offDD,
                                                h_, nullptr, nullptr, nullptr, D_, D_);

        rmsnorm_kernel<1><<<NT_, 256>>>(h_, ffn_n + i * D_, nullptr, ah_, al_);
        gemm_bf2<128, 64, 2, 2, 2><<<gF, 128>>>(ah_, al_, w1h_ + offFD, w1l_ + offFD,
                                                g1_, nullptr, nullptr, nullptr, F_, D_);
        gemm_bf2<128, 64, 2, 2, 3><<<gF, 128>>>(ah_, al_, w3h_ + offFD, w3l_ + offFD,
                                                nullptr, g1_, uh_, ul_, F_, D_);
        gemm_bf2<64, 64, 2, 2, 1><<<gDs, 128>>>(uh_, ul_, w2h_ + offFD, w2l_ + offFD,
                                                h_, nullptr, nullptr, nullptr, D_, F_);
    }

    rmsnorm_kernel<0><<<NT_, 256>>>(h_, out_n, a_, nullptr, nullptr);
    gemm_tc<128, 128, 2, 4, 0><<<gTF, 256>>>(a_, w_out, out, V_, D_);  // logits
    gemm_tc<128, 128, 2, 4, 4><<<gTF, 256>>>(a_, w_ctx, c_,  V_, D_);  // c + softplus

    corr_kernel<<<(S_ + 255) / 256, 256>>>(y);
    ctx_scan_kernel<<<dim3((V_ + 255) / 256, B_, S_ / CTX_CHUNK), 256>>>(out, conv_w);
    nll_kernel<<<NT_, 256>>>(out, y);
    finalize_kernel<<<1, 1>>>(out);
}

// round 10
// speedup vs baseline: 1.0872x; 1.0872x over previous
#include <cuda_runtime.h>
#include <cuda_fp16.h>
#include <math.h>
#include <stdint.h>

#define B_  2
#define S_  512
#define V_  32000
#define D_  768
#define F_  2048
#define L_  4
#define H_  12
#define HD_ 64
#define FCS_ 8
#define YW_ (S_ + FCS_ - 1)   /* 519 */
#define NT_ (B_ * S_)         /* 1024 rows */

// ---------------- static scratch (allocation-free rule) ----------------
__device__ float  g_h [NT_ * D_];
__device__ float  g_a [NT_ * D_];          // fp32 rmsnorm out (heads)
__device__ float  g_q [NT_ * D_];
__device__ float  g_k [NT_ * D_];
__device__ float  g_v [NT_ * D_];
__device__ float  g_g1[NT_ * F_];
__device__ float  g_c [NT_ * V_];          // context head logits c (131 MB)
__device__ float2 g_rope[S_ * 32];
__device__ double g_acc[4];                // [0]=softplus [1]=delta [2]=nll [3]=valid

// fp16 activations (hi + optional lo residual)
__device__ __align__(16) __half g_ah[NT_ * D_], g_al[NT_ * D_];
__device__ __align__(16) __half g_oh[NT_ * D_];
__device__ __align__(16) __half g_uh[NT_ * F_], g_ul[NT_ * F_];

// fp16 weights (converted once per launch)
__device__ __align__(16) __half g_wq[L_*D_*D_];
__device__ __align__(16) __half g_wk[L_*D_*D_];
__device__ __align__(16) __half g_wv[L_*D_*D_];
__device__ __align__(16) __half g_wo[L_*D_*D_];
__device__ __align__(16) __half g_w1[L_*F_*D_];
__device__ __align__(16) __half g_w3[L_*F_*D_];
__device__ __align__(16) __half g_w2[L_*D_*F_];

__device__ __forceinline__ float softplusf(float x) {
    if (x > 15.0f) return x;
    return log1pf(expf(x));
}

__device__ __forceinline__ uint32_t f2tf32(float x) {
    uint32_t r; asm("cvt.rna.tf32.f32 %0, %1;" : "=r"(r) : "f"(x)); return r;
}

__device__ __forceinline__ void mma_tf32(float& c0, float& c1, float& c2, float& c3,
                                         uint32_t a0, uint32_t a1, uint32_t a2, uint32_t a3,
                                         uint32_t b0, uint32_t b1) {
    asm volatile("mma.sync.aligned.m16n8k8.row.col.f32.tf32.tf32.f32 "
                 "{%0,%1,%2,%3}, {%4,%5,%6,%7}, {%8,%9}, {%0,%1,%2,%3};"
                 : "+f"(c0), "+f"(c1), "+f"(c2), "+f"(c3)
                 : "r"(a0), "r"(a1), "r"(a2), "r"(a3), "r"(b0), "r"(b1));
}

__device__ __forceinline__ void mma_f16(float& c0, float& c1, float& c2, float& c3,
                                        uint32_t a0, uint32_t a1, uint32_t a2, uint32_t a3,
                                        uint32_t b0, uint32_t b1) {
    asm volatile("mma.sync.aligned.m16n8k16.row.col.f32.f16.f16.f32 "
                 "{%0,%1,%2,%3}, {%4,%5,%6,%7}, {%8,%9}, {%0,%1,%2,%3};"
                 : "+f"(c0), "+f"(c1), "+f"(c2), "+f"(c3)
                 : "r"(a0), "r"(a1), "r"(a2), "r"(a3), "r"(b0), "r"(b1));
}

__global__ void zero_acc_kernel() {
    if (threadIdx.x < 4) g_acc[threadIdx.x] = 0.0;
}

// ---------------- weight convert fp32 -> fp16 (float4 vectorized) ----------------
__global__ void wconv_kernel(const float* __restrict__ src, __half* __restrict__ dst, int n4) {
    int i = blockIdx.x * blockDim.x + threadIdx.x;
    if (i >= n4) return;
    float4 v = ((const float4*)src)[i];
    __half2 h01 = __floats2half2_rn(v.x, v.y);
    __half2 h23 = __floats2half2_rn(v.z, v.w);
    ((__half2*)dst)[2 * i]     = h01;
    ((__half2*)dst)[2 * i + 1] = h23;
}

// ---------------- embedding gather ----------------
__global__ void embed_kernel(const int* __restrict__ x, const float* __restrict__ emb) {
    int i = blockIdx.x * blockDim.x + threadIdx.x;
    if (i >= NT_ * D_) return;
    int row = i / D_;
    int d   = i - row * D_;
    g_h[i] = emb[(size_t)x[row] * D_ + d];
}

// ---------------- rmsnorm (SPLIT: 0=fp32, 1=fp16 hi, 2=fp16 hi+lo) ----------------
template<int SPLIT>
__global__ void rmsnorm_kernel(const float* __restrict__ in, const float* __restrict__ w,
                               float* __restrict__ out,
                               __half* __restrict__ oh, __half* __restrict__ ol) {
    int row = blockIdx.x;
    const float* ip = in + row * D_;
    __shared__ float red[256];
    float ss = 0.f;
    for (int d = threadIdx.x; d < D_; d += 256) { float v = ip[d]; ss += v * v; }
    red[threadIdx.x] = ss; __syncthreads();
    for (int st = 128; st > 0; st >>= 1) {
        if (threadIdx.x < st) red[threadIdx.x] += red[threadIdx.x + st];
        __syncthreads();
    }
    float rs = rsqrtf(red[0] / (float)D_ + 1e-5f);
    for (int d = threadIdx.x; d < D_; d += 256) {
        float v = ip[d] * rs * w[d];
        if (SPLIT == 0) {
            out[row * D_ + d] = v;
        } else {
            __half h = __float2half_rn(v);
            oh[row * D_ + d] = h;
            if (SPLIT == 2) ol[row * D_ + d] = __float2half_rn(v - __half2float(h));
        }
    }
}

#define TLD 20   /* smem row stride (u32): fragment loads conflict-free */

// =======================================================================
//  tf32 tensor-core NT-GEMM (head projections; validated path)
//  EPI: 0=store 4=store+softplus-sum
// =======================================================================
template<int BM, int BN, int WM, int WN, int EPI>
__global__ __launch_bounds__(WM * WN * 32)
void gemm_tc(const float* __restrict__ A, const float* __restrict__ Bw,
             float* __restrict__ C, int N, int K) {
    constexpr int THREADS = WM * WN * 32;
    constexpr int WTM = BM / WM;
    constexpr int WTN = BN / WN;
    constexpr int MT  = WTM / 16;
    constexpr int NTT = WTN / 8;
    constexpr int RPP = THREADS / 2;
    constexpr int NLA = BM / RPP;
    constexpr int NLB = BN / RPP;

    __shared__ uint32_t As[2][BM][TLD];
    __shared__ uint32_t Bs[2][BN][TLD];
    __shared__ float sred[THREADS];

    const int tid  = threadIdx.x;
    const int lane = tid & 31;
    const int wid  = tid >> 5;
    const int wm   = wid / WN;
    const int wn   = wid % WN;
    const int bm   = blockIdx.x * BM;
    const int bn   = blockIdx.y * BN;

    const int lr = tid >> 1;
    const int ks = (tid & 1) * 8;
    const float* Ag = A  + (size_t)(bm + lr) * K + ks;
    const float* Bg = Bw + (size_t)(bn + lr) * K + ks;

    float acc[MT][NTT][4];
#pragma unroll
    for (int i = 0; i < MT; i++)
#pragma unroll
        for (int j = 0; j < NTT; j++)
#pragma unroll
            for (int q = 0; q < 4; q++) acc[i][j][q] = 0.f;

    float4 pa[NLA][2], pb[NLB][2];

#pragma unroll
    for (int l = 0; l < NLA; l++) {
        pa[l][0] = *(const float4*)(Ag + (size_t)l * RPP * K);
        pa[l][1] = *(const float4*)(Ag + (size_t)l * RPP * K + 4);
    }
#pragma unroll
    for (int l = 0; l < NLB; l++) {
        pb[l][0] = *(const float4*)(Bg + (size_t)l * RPP * K);
        pb[l][1] = *(const float4*)(Bg + (size_t)l * RPP * K + 4);
    }

    auto store_tiles = [&](int buf) {
#pragma unroll
        for (int l = 0; l < NLA; l++) {
            uint4 u0 = make_uint4(f2tf32(pa[l][0].x), f2tf32(pa[l][0].y),
                                  f2tf32(pa[l][0].z), f2tf32(pa[l][0].w));
            uint4 u1 = make_uint4(f2tf32(pa[l][1].x), f2tf32(pa[l][1].y),
                                  f2tf32(pa[l][1].z), f2tf32(pa[l][1].w));
            *(uint4*)&As[buf][lr + l * RPP][ks]     = u0;
            *(uint4*)&As[buf][lr + l * RPP][ks + 4] = u1;
        }
#pragma unroll
        for (int l = 0; l < NLB; l++) {
            uint4 u0 = make_uint4(f2tf32(pb[l][0].x), f2tf32(pb[l][0].y),
                                  f2tf32(pb[l][0].z), f2tf32(pb[l][0].w));
            uint4 u1 = make_uint4(f2tf32(pb[l][1].x), f2tf32(pb[l][1].y),
                                  f2tf32(pb[l][1].z), f2tf32(pb[l][1].w));
            *(uint4*)&Bs[buf][lr + l * RPP][ks]     = u0;
            *(uint4*)&Bs[buf][lr + l * RPP][ks + 4] = u1;
        }
    };

    store_tiles(0);
    __syncthreads();

    const int nk = K / 16;
    for (int kc = 0; kc < nk; kc++) {
        const int cur = kc & 1;
        if (kc + 1 < nk) {
            const float* Ap = Ag + (kc + 1) * 16;
            const float* Bp = Bg + (kc + 1) * 16;
#pragma unroll
            for (int l = 0; l < NLA; l++) {
                pa[l][0] = *(const float4*)(Ap + (size_t)l * RPP * K);
                pa[l][1] = *(const float4*)(Ap + (size_t)l * RPP * K + 4);
            }
#pragma unroll
            for (int l = 0; l < NLB; l++) {
                pb[l][0] = *(const float4*)(Bp + (size_t)l * RPP * K);
                pb[l][1] = *(const float4*)(Bp + (size_t)l * RPP * K + 4);
            }
        }

#pragma unroll
        for (int kk = 0; kk < 2; kk++) {
            const int kq = kk * 8 + (lane & 3);
            uint32_t af[MT][4], bf[NTT][2];
#pragma unroll
            for (int mt = 0; mt < MT; mt++) {
                int row = wm * WTM + mt * 16 + (lane >> 2);
                af[mt][0] = As[cur][row][kq];
                af[mt][1] = As[cur][row + 8][kq];
                af[mt][2] = As[cur][row][kq + 4];
                af[mt][3] = As[cur][row + 8][kq + 4];
            }
#pragma unroll
            for (int nt = 0; nt < NTT; nt++) {
                int nr = wn * WTN + nt * 8 + (lane >> 2);
                bf[nt][0] = Bs[cur][nr][kq];
                bf[nt][1] = Bs[cur][nr][kq + 4];
            }
#pragma unroll
            for (int mt = 0; mt < MT; mt++)
#pragma unroll
                for (int nt = 0; nt < NTT; nt++)
                    mma_tf32(acc[mt][nt][0], acc[mt][nt][1],
                             acc[mt][nt][2], acc[mt][nt][3],
                             af[mt][0], af[mt][1], af[mt][2], af[mt][3],
                             bf[nt][0], bf[nt][1]);
        }

        if (kc + 1 < nk) store_tiles(cur ^ 1);
        __syncthreads();
    }

    float spsum = 0.f;
#pragma unroll
    for (int mt = 0; mt < MT; mt++) {
        int row = bm + wm * WTM + mt * 16 + (lane >> 2);
#pragma unroll
        for (int nt = 0; nt < NTT; nt++) {
            int col = bn + wn * WTN + nt * 8 + (lane & 3) * 2;
            float* a4 = acc[mt][nt];
            size_t i0 = (size_t)row * N + col;
            size_t i1 = (size_t)(row + 8) * N + col;
            if (EPI == 4) {
                spsum += softplusf(a4[0]) + softplusf(a4[1]) +
                         softplusf(a4[2]) + softplusf(a4[3]);
            }
            *(float2*)(C + i0) = make_float2(a4[0], a4[1]);
            *(float2*)(C + i1) = make_float2(a4[2], a4[3]);
        }
    }
    if (EPI == 4) {
        sred[tid] = spsum; __syncthreads();
        for (int st = THREADS / 2; st > 0; st >>= 1) {
            if (tid < st) sred[tid] += sred[tid + st];
            __syncthreads();
        }
        if (tid == 0) atomicAdd(&g_acc[0], (double)sred[0]);
    }
}

// =======================================================================
//  fp16 NT-GEMM:  C[m,n] (op)= sum_k A[m,k]*W[n,k]
//  NI=1: A=hi only (1 mma/k16).  NI=2: A=hi+lo residual (2 mma/k16,
//  only B rounds).  B is plain fp16.  Fragment layout = validated rd8 map.
//  EPI: 0=store 1=add 2=silu 3=mulG->fp16 hi/lo
// =======================================================================
template<int BM, int BN, int WM, int WN, int EPI, int NI>
__device__ __forceinline__ void gemm_f16_core(const __half* __restrict__ Ah,
                                              const __half* __restrict__ Al,
                                              const __half* __restrict__ Bw,
                                              float* __restrict__ C,
                                              const float* __restrict__ G,
                                              __half* __restrict__ Oh,
                                              __half* __restrict__ Ol,
                                              int N, int K, int bm, int bn) {
    constexpr int THREADS = WM * WN * 32;
    constexpr int WTM = BM / WM;
    constexpr int WTN = BN / WN;
    constexpr int MT  = WTM / 16;
    constexpr int NTT = WTN / 8;
    constexpr int RPP = THREADS / 2;
    constexpr int NLA = BM / RPP;
    constexpr int NLB = BN / RPP;

    __shared__ uint32_t As[2][BM][TLD];
    __shared__ uint32_t Bs[2][BN][TLD];

    const int tid  = threadIdx.x;
    const int lane = tid & 31;
    const int wid  = tid >> 5;
    const int wm   = wid / WN;
    const int wn   = wid % WN;

    const int lr = tid >> 1;
    const int ks = (tid & 1) * 8;   // element offset 0/8 in k16 chunk
    const int js = ks >> 1;         // u32 pair offset 0/4
    const __half* Agh = Ah + (size_t)(bm + lr) * K + ks;
    const __half* Agl = (NI == 2) ? Al + (size_t)(bm + lr) * K + ks : nullptr;
    const __half* Bg  = Bw + (size_t)(bn + lr) * K + ks;

    float acc[MT][NTT][4];
#pragma unroll
    for (int i = 0; i < MT; i++)
#pragma unroll
        for (int j = 0; j < NTT; j++)
#pragma unroll
            for (int q = 0; q < 4; q++) acc[i][j][q] = 0.f;

    uint4 pah[NLA], pal[NLA], pbh[NLB];

#pragma unroll
    for (int l = 0; l < NLA; l++) {
        pah[l] = *(const uint4*)(Agh + (size_t)l * RPP * K);
        if (NI == 2) pal[l] = *(const uint4*)(Agl + (size_t)l * RPP * K);
    }
#pragma unroll
    for (int l = 0; l < NLB; l++)
        pbh[l] = *(const uint4*)(Bg + (size_t)l * RPP * K);

    auto store_tiles = [&](int buf) {
#pragma unroll
        for (int l = 0; l < NLA; l++) {
            *(uint4*)&As[buf][lr + l * RPP][js] = pah[l];
            if (NI == 2) *(uint4*)&As[buf][lr + l * RPP][8 + js] = pal[l];
        }
#pragma unroll
        for (int l = 0; l < NLB; l++)
            *(uint4*)&Bs[buf][lr + l * RPP][js] = pbh[l];
    };

    store_tiles(0);
    __syncthreads();

    const int nk = K / 16;
    for (int kc = 0; kc < nk; kc++) {
        const int cur = kc & 1;
        if (kc + 1 < nk) {
            const int off = (kc + 1) * 16;
#pragma unroll
            for (int l = 0; l < NLA; l++) {
                pah[l] = *(const uint4*)(Agh + (size_t)l * RPP * K + off);
                if (NI == 2) pal[l] = *(const uint4*)(Agl + (size_t)l * RPP * K + off);
            }
#pragma unroll
            for (int l = 0; l < NLB; l++)
                pbh[l] = *(const uint4*)(Bg + (size_t)l * RPP * K + off);
        }

        {
            const int jq = lane & 3;
            uint32_t ah[MT][4], al[MT][4], bh[NTT][2];
#pragma unroll
            for (int mt = 0; mt < MT; mt++) {
                int row = wm * WTM + mt * 16 + (lane >> 2);
                ah[mt][0] = As[cur][row][jq];
                ah[mt][1] = As[cur][row + 8][jq];
                ah[mt][2] = As[cur][row][jq + 4];
                ah[mt][3] = As[cur][row + 8][jq + 4];
                if (NI == 2) {
                    al[mt][0] = As[cur][row][jq + 8];
                    al[mt][1] = As[cur][row + 8][jq + 8];
                    al[mt][2] = As[cur][row][jq + 12];
                    al[mt][3] = As[cur][row + 8][jq + 12];
                }
            }
#pragma unroll
            for (int nt = 0; nt < NTT; nt++) {
                int nr = wn * WTN + nt * 8 + (lane >> 2);
                bh[nt][0] = Bs[cur][nr][jq];
                bh[nt][1] = Bs[cur][nr][jq + 4];
            }
#pragma unroll
            for (int mt = 0; mt < MT; mt++)
#pragma unroll
                for (int nt = 0; nt < NTT; nt++) {
                    mma_f16(acc[mt][nt][0], acc[mt][nt][1], acc[mt][nt][2], acc[mt][nt][3],
                            ah[mt][0], ah[mt][1], ah[mt][2], ah[mt][3],
                            bh[nt][0], bh[nt][1]);
                    if (NI == 2)
                        mma_f16(acc[mt][nt][0], acc[mt][nt][1], acc[mt][nt][2], acc[mt][nt][3],
                                al[mt][0], al[mt][1], al[mt][2], al[mt][3],
                                bh[nt][0], bh[nt][1]);
                }
        }

        if (kc + 1 < nk) store_tiles(cur ^ 1);
        __syncthreads();
    }

    // ---------------- epilogue ----------------
#pragma unroll
    for (int mt = 0; mt < MT; mt++) {
        int row = bm + wm * WTM + mt * 16 + (lane >> 2);
#pragma unroll
        for (int nt = 0; nt < NTT; nt++) {
            int col = bn + wn * WTN + nt * 8 + (lane & 3) * 2;
            float* a4 = acc[mt][nt];
            size_t i0 = (size_t)row * N + col;
            size_t i1 = (size_t)(row + 8) * N + col;
            float2 r0 = make_float2(a4[0], a4[1]);
            float2 r1 = make_float2(a4[2], a4[3]);
            if (EPI == 1) {
                float2 o0 = *(const float2*)(C + i0);
                float2 o1 = *(const float2*)(C + i1);
                r0.x += o0.x; r0.y += o0.y;
                r1.x += o1.x; r1.y += o1.y;
            } else if (EPI == 2) {
                r0.x = r0.x / (1.f + expf(-r0.x));
                r0.y = r0.y / (1.f + expf(-r0.y));
                r1.x = r1.x / (1.f + expf(-r1.x));
                r1.y = r1.y / (1.f + expf(-r1.y));
            } else if (EPI == 3) {
                float2 g0 = *(const float2*)(G + i0);
                float2 g1v = *(const float2*)(G + i1);
                r0.x *= g0.x; r0.y *= g0.y;
                r1.x *= g1v.x; r1.y *= g1v.y;
            }
            if (EPI == 3) {
                __half2 h0 = __floats2half2_rn(r0.x, r0.y);
                __half2 h1 = __floats2half2_rn(r1.x, r1.y);
                __half2 l0 = __floats2half2_rn(r0.x - __half2float(__low2half(h0)),
                                               r0.y - __half2float(__high2half(h0)));
                __half2 l1 = __floats2half2_rn(r1.x - __half2float(__low2half(h1)),
                                               r1.y - __half2float(__high2half(h1)));
                *(__half2*)(Oh + i0) = h0;
                *(__half2*)(Oh + i1) = h1;
                *(__half2*)(Ol + i0) = l0;
                *(__half2*)(Ol + i1) = l1;
            } else {
                *(float2*)(C + i0) = r0;
                *(float2*)(C + i1) = r1;
            }
        }
    }
}

template<int BM, int BN, int WM, int WN, int EPI, int NI>
__global__ __launch_bounds__(WM * WN * 32)
void gemm_f16(const __half* __restrict__ Ah, const __half* __restrict__ Al,
              const __half* __restrict__ Bw,
              float* __restrict__ C, const float* __restrict__ G,
              __half* __restrict__ Oh, __half* __restrict__ Ol, int N, int K) {
    gemm_f16_core<BM, BN, WM, WN, EPI, NI>(Ah, Al, Bw, C, G, Oh, Ol, N, K,
                                           blockIdx.x * BM, blockIdx.y * BN);
}

// fused q/k/v (blockIdx.z selects weight/output), plain fp16
__global__ __launch_bounds__(128)
void gemm_qkv_f16(const __half* __restrict__ Ah, int layer_off,
                  float* __restrict__ C0, float* __restrict__ C1, float* __restrict__ C2,
                  int N, int K) {
    const __half* Bz; float* Cz;
    if (blockIdx.z == 0)      { Bz = g_wq + layer_off; Cz = C0; }
    else if (blockIdx.z == 1) { Bz = g_wk + layer_off; Cz = C1; }
    else                      { Bz = g_wv + layer_off; Cz = C2; }
    gemm_f16_core<64, 64, 2, 2, 0, 1>(Ah, nullptr, Bz, Cz, nullptr, nullptr, nullptr,
                                      N, K, blockIdx.x * 64, blockIdx.y * 64);
}

// ---------------- RoPE ----------------
__global__ void rope_table_kernel() {
    int i = blockIdx.x * blockDim.x + threadIdx.x;
    if (i >= S_ * 32) return;
    int s = i / 32, p = i - (i / 32) * 32;
    float f   = expf((float)(2 * p) * (-logf(10000.0f) / (float)HD_));
    float ang = (float)s * f;
    double a  = (double)ang;
    g_rope[i] = make_float2((float)cos(a), (float)sin(a));
}

__global__ void rope_apply_kernel() {
    int idx = blockIdx.x * blockDim.x + threadIdx.x;          // over B*S*H*32
    if (idx >= B_ * S_ * H_ * 32) return;
    int p = idx & 31;
    int h = (idx >> 5) % H_;
    int s = (idx / (32 * H_)) % S_;
    int b = idx / (32 * H_ * S_);
    float2 cs = g_rope[s * 32 + p];
    int base = ((b * S_ + s) * D_) + h * HD_ + 2 * p;
    float xr, xi;
    xr = g_q[base]; xi = g_q[base + 1];
    g_q[base]     = xr * cs.x - xi * cs.y;
    g_q[base + 1] = xr * cs.y + xi * cs.x;
    xr = g_k[base]; xi = g_k[base + 1];
    g_k[base]     = xr * cs.x - xi * cs.y;
    g_k[base + 1] = xr * cs.y + xi * cs.x;
}

// ---------------- flash-style attention (writes o as fp16 hi) ----------------
__global__ __launch_bounds__(256)
void attn_flash() {
    const int qt = blockIdx.x;
    const int bh = blockIdx.y;
    const int b = bh / H_, h = bh - (bh / H_) * H_;
    const int tid = threadIdx.x;
    const int q  = tid >> 2;
    const int dg = (tid & 3) * 16;
    const int q0 = qt * 64;

    __shared__ float KS[64][68];
    __shared__ float Vs[64][68];
    __shared__ float rowm[64], rows[64], cfs[64];

    float4 qr[16];
    const float* qp = g_q + ((size_t)(b * S_ + q0 + q)) * D_ + h * HD_;
#pragma unroll
    for (int j = 0; j < 16; j++) qr[j] = *(const float4*)(qp + 4 * j);

    float acc[16];
#pragma unroll
    for (int j = 0; j < 16; j++) acc[j] = 0.f;
    if (tid < 64) { rowm[tid] = -1e30f; rows[tid] = 0.f; }

    for (int k0 = 0; k0 <= q0; k0 += 64) {
        {
            int r = tid >> 2, c = (tid & 3) * 16;
            const float* kp = g_k + ((size_t)(b * S_ + k0 + r)) * D_ + h * HD_ + c;
            const float* vp = g_v + ((size_t)(b * S_ + k0 + r)) * D_ + h * HD_ + c;
#pragma unroll
            for (int j = 0; j < 4; j++) {
                *(float4*)&KS[r][c + 4 * j] = *(const float4*)(kp + 4 * j);
                *(float4*)&Vs[r][c + 4 * j] = *(const float4*)(vp + 4 * j);
            }
        }
        __syncthreads();

        float sreg[16];
        {
            const int kb = (tid & 3) * 16;
#pragma unroll
            for (int j = 0; j < 16; j++) {
                int kk = kb + j;
                float d = 0.f;
#pragma unroll
                for (int t4 = 0; t4 < 16; t4++) {
                    float4 kv = *(const float4*)&KS[kk][4 * t4];
                    d += qr[t4].x * kv.x + qr[t4].y * kv.y +
                         qr[t4].z * kv.z + qr[t4].w * kv.w;
                }
                sreg[j] = (k0 + kk <= q0 + q) ? d * 0.125f : -1e30f;
            }
        }
        __syncthreads();

        {
            const int kb = (tid & 3) * 16;
#pragma unroll
            for (int j = 0; j < 16; j++) KS[q][kb + j] = sreg[j];
        }
        __syncthreads();

        if (tid < 64) {
            float mo = rowm[tid];
            float tm = mo;
#pragma unroll 8
            for (int kk = 0; kk < 64; kk++) tm = fmaxf(tm, KS[tid][kk]);
            float cf = expf(mo - tm);
            float ps = 0.f;
#pragma unroll 8
            for (int kk = 0; kk < 64; kk++) {
                float p = expf(KS[tid][kk] - tm);
                KS[tid][kk] = p;
                ps += p;
            }
            rowm[tid] = tm;
            rows[tid] = rows[tid] * cf + ps;
            cfs[tid] = cf;
        }
        __syncthreads();

        {
            float cf = cfs[q];
#pragma unroll
            for (int j = 0; j < 16; j++) acc[j] *= cf;
            for (int kk = 0; kk < 64; kk++) {
                float p = KS[q][kk];
#pragma unroll
                for (int j4 = 0; j4 < 4; j4++) {
                    float4 vv = *(const float4*)&Vs[kk][dg + 4 * j4];
                    acc[4 * j4 + 0] += p * vv.x;
                    acc[4 * j4 + 1] += p * vv.y;
                    acc[4 * j4 + 2] += p * vv.z;
                    acc[4 * j4 + 3] += p * vv.w;
                }
            }
        }
        __syncthreads();
    }

    float inv = 1.f / rows[q];
    size_t base = ((size_t)(b * S_ + q0 + q)) * D_ + h * HD_ + dg;
#pragma unroll
    for (int j2 = 0; j2 < 8; j2++) {
        float v0 = acc[2 * j2] * inv, v1 = acc[2 * j2 + 1] * inv;
        *(__half2*)(g_oh + base + 2 * j2) = __floats2half2_rn(v0, v1);
    }
}

// ---------------- sparse BCE correction ----------------
__global__ void corr_kernel(const int* __restrict__ y) {
    int s = blockIdx.x * blockDim.x + threadIdx.x;
    if (s >= S_) return;
    int tok[2][FCS_];
    for (int b = 0; b < 2; b++)
        for (int j = 0; j < FCS_; j++)
            tok[b][j] = y[b * YW_ + (FCS_ - 1) + ((s - (FCS_ - 1) + j + S_) & (S_ - 1))];
    double dsum = 0.0;
    for (int b = 0; b < 2; b++)
        for (int j = 0; j < FCS_; j++) {
            int v = tok[b][j];
            bool first = true;
            for (int b2 = 0; b2 <= b && first; b2++) {
                int jmax = (b2 == b) ? j : FCS_;
                for (int j2 = 0; j2 < jmax; j2++)
                    if (tok[b2][j2] == v) { first = false; break; }
            }
            if (!first) continue;
            int c0 = 0, c1 = 0;
            for (int j2 = 0; j2 < FCS_; j2++) {
                c0 += (tok[0][j2] == v);
                c1 += (tok[1][j2] == v);
            }
            float w = (c0 > 1 || c1 > 1) ? 1.5f : 1.0f;
            for (int b2 = 0; b2 < 2; b2++) {
                float cv = g_c[((size_t)(b2 * S_ + s)) * V_ + v];
                float t  = ((b2 == 0 ? c0 : c1) > 0) ? 1.f : 0.f;
                dsum += (double)((w - 1.f) * softplusf(cv) - w * t * cv);
            }
        }
    atomicAdd(&g_acc[1], dsum);
}

// ---------------- logits += exp-kernel context (ring-buffer window) ----
#define CTX_CHUNK 128
__global__ void ctx_scan_kernel(float* __restrict__ logits, const float* __restrict__ conv_w) {
    int v = blockIdx.x * blockDim.x + threadIdx.x;
    if (v >= V_) return;
    int b  = blockIdx.y;
    int s0 = blockIdx.z * CTX_CHUNK;
    float e = expf(-conv_w[0]);

    float pw[FCS_];
    pw[FCS_ - 1] = 1.f;
#pragma unroll
    for (int d = FCS_ - 1; d >= 1; --d) pw[d - 1] = pw[d] * e;

    float ring[FCS_];
#pragma unroll
    for (int j = 1; j <= FCS_; j++) {
        int sp = s0 - j;
        ring[(8 - j) & 7] = (sp >= 0) ? g_c[((size_t)(b * S_ + sp)) * V_ + v] : 0.f;
    }

    for (int t = 0; t < CTX_CHUNK / 8; t++) {
#pragma unroll
        for (int u = 0; u < 8; u++) {
            int s = s0 + 8 * t + u;
            size_t idx = ((size_t)(b * S_ + s)) * V_ + v;
            float ctx = 0.f;
#pragma unroll
            for (int d = 1; d <= FCS_; d++)
                ctx += pw[d - 1] * ring[(u - d) & 7];
            logits[idx] += ctx;
            ring[u] = g_c[idx];
        }
    }
}

// ---------------- NLL ----------------
__global__ void nll_kernel(const float* __restrict__ logits, const int* __restrict__ y) {
    int row = blockIdx.x;
    int b = row / S_, s = row - (row / S_) * S_;
    const float* lp = logits + (size_t)row * V_;
    __shared__ float red[256];
    float m = -1e30f;
    for (int v = threadIdx.x; v < V_; v += 256) m = fmaxf(m, lp[v]);
    red[threadIdx.x] = m; __syncthreads();
    for (int st = 128; st > 0; st >>= 1) {
        if (threadIdx.x < st) red[threadIdx.x] = fmaxf(red[threadIdx.x], red[threadIdx.x + st]);
        __syncthreads();
    }
    m = red[0];
    __syncthreads();
    float ssum = 0.f;
    for (int v = threadIdx.x; v < V_; v += 256) ssum += expf(lp[v] - m);
    red[threadIdx.x] = ssum; __syncthreads();
    for (int st = 128; st > 0; st >>= 1) {
        if (threadIdx.x < st) red[threadIdx.x] += red[threadIdx.x + st];
        __syncthreads();
    }
    if (threadIdx.x == 0) {
        int yt = y[b * YW_ + s];
        if (yt != -1) {
            float lse = m + logf(red[0]);
            atomicAdd(&g_acc[2], (double)(lse - lp[yt]));
            atomicAdd(&g_acc[3], 1.0);
        }
    }
}

__global__ void finalize_kernel(float* __restrict__ out) {
    double cnt = g_acc[3] < 1.0 ? 1.0 : g_acc[3];
    out[(size_t)NT_ * V_]     = (float)(g_acc[2] / cnt);
    out[(size_t)NT_ * V_ + 1] = (float)((g_acc[0] + g_acc[1]) / ((double)NT_ * (double)V_));
}

// ---------------- launcher ----------------
extern "C" void kernel_launch(void* const* d_in, const int* in_sizes, int n_in,
                              void* d_out, int out_size) {
    const int*   x      = (const int*)  d_in[0];
    const int*   y      = (const int*)  d_in[1];
    const float* emb    = (const float*)d_in[2];
    const float* wq     = (const float*)d_in[3];
    const float* wk     = (const float*)d_in[4];
    const float* wv     = (const float*)d_in[5];
    const float* wo     = (const float*)d_in[6];
    const float* w1     = (const float*)d_in[7];
    const float* w2     = (const float*)d_in[8];
    const float* w3     = (const float*)d_in[9];
    const float* attn_n = (const float*)d_in[10];
    const float* ffn_n  = (const float*)d_in[11];
    const float* out_n  = (const float*)d_in[12];
    const float* w_out  = (const float*)d_in[13];
    const float* w_ctx  = (const float*)d_in[14];
    const float* conv_w = (const float*)d_in[15];
    float* out = (float*)d_out;

    float *h_, *a_, *q_, *k_, *v_, *g1_, *c_;
    __half *ah_, *al_, *oh_, *uh_, *ul_;
    __half *wq_f, *wk_f, *wv_f, *wo_f, *w1_f, *w3_f, *w2_f;
    cudaGetSymbolAddress((void**)&h_,  g_h);
    cudaGetSymbolAddress((void**)&a_,  g_a);
    cudaGetSymbolAddress((void**)&q_,  g_q);
    cudaGetSymbolAddress((void**)&k_,  g_k);
    cudaGetSymbolAddress((void**)&v_,  g_v);
    cudaGetSymbolAddress((void**)&g1_, g_g1);
    cudaGetSymbolAddress((void**)&c_,  g_c);
    cudaGetSymbolAddress((void**)&ah_, g_ah);
    cudaGetSymbolAddress((void**)&al_, g_al);
    cudaGetSymbolAddress((void**)&oh_, g_oh);
    cudaGetSymbolAddress((void**)&uh_, g_uh);
    cudaGetSymbolAddress((void**)&ul_, g_ul);
    cudaGetSymbolAddress((void**)&wq_f, g_wq);
    cudaGetSymbolAddress((void**)&wk_f, g_wk);
    cudaGetSymbolAddress((void**)&wv_f, g_wv);
    cudaGetSymbolAddress((void**)&wo_f, g_wo);
    cudaGetSymbolAddress((void**)&w1_f, g_w1);
    cudaGetSymbolAddress((void**)&w3_f, g_w3);
    cudaGetSymbolAddress((void**)&w2_f, g_w2);

    zero_acc_kernel<<<1, 32>>>();
    embed_kernel<<<(NT_ * D_ + 255) / 256, 256>>>(x, emb);
    rope_table_kernel<<<(S_ * 32 + 255) / 256, 256>>>();

    // weight converts (fp32 -> fp16, whole tensors)
    {
        int nDD4 = L_ * D_ * D_ / 4;
        int nFD4 = L_ * F_ * D_ / 4;
        wconv_kernel<<<(nDD4 + 255) / 256, 256>>>(wq, wq_f, nDD4);
        wconv_kernel<<<(nDD4 + 255) / 256, 256>>>(wk, wk_f, nDD4);
        wconv_kernel<<<(nDD4 + 255) / 256, 256>>>(wv, wv_f, nDD4);
        wconv_kernel<<<(nDD4 + 255) / 256, 256>>>(wo, wo_f, nDD4);
        wconv_kernel<<<(nFD4 + 255) / 256, 256>>>(w1, w1_f, nFD4);
        wconv_kernel<<<(nFD4 + 255) / 256, 256>>>(w3, w3_f, nFD4);
        wconv_kernel<<<(nFD4 + 255) / 256, 256>>>(w2, w2_f, nFD4);
    }

    dim3 gQKV(NT_ / 64, D_ / 64, 3);     // 16 x 12 x 3 (64x64 tiles)
    dim3 gDs (NT_ / 64, D_ / 64);        // 16 x 12
    dim3 gF  (NT_ / 128, F_ / 64);       // 8 x 32 (128x64 tiles)
    dim3 gHD (NT_ / 128, V_ / 128);      // 8 x 250 (m fast for L2 weight reuse)

    for (int i = 0; i < L_; i++) {
        int offDD = i * D_ * D_;
        int offFD = i * F_ * D_;

        // attn path: plain fp16 (1 mma/k16)
        rmsnorm_kernel<1><<<NT_, 256>>>(h_, attn_n + i * D_, nullptr, ah_, nullptr);
        gemm_qkv_f16<<<gQKV, 128>>>(ah_, offDD, q_, k_, v_, D_, D_);
        rope_apply_kernel<<<(B_ * S_ * H_ * 32 + 255) / 256, 256>>>();
        attn_flash<<<dim3(S_ / 64, B_ * H_), 256>>>();
        gemm_f16<64, 64, 2, 2, 1, 1><<<gDs, 128>>>(oh_, nullptr, wo_f + offDD,
                                                   h_, nullptr, nullptr, nullptr, D_, D_);

        // ffn path: A-split fp16 (2 mma/k16; only weights round)
        rmsnorm_kernel<2><<<NT_, 256>>>(h_, ffn_n + i * D_, nullptr, ah_, al_);
        gemm_f16<128, 64, 2, 2, 2, 2><<<gF, 128>>>(ah_, al_, w1_f + offFD,
                                                   g1_, nullptr, nullptr, nullptr, F_, D_);
        gemm_f16<128, 64, 2, 2, 3, 2><<<gF, 128>>>(ah_, al_, w3_f + offFD,
                                                   nullptr, g1_, uh_, ul_, F_, D_);
        gemm_f16<64, 64, 2, 2, 1, 2><<<gDs, 128>>>(uh_, ul_, w2_f + offFD,
                                                   h_, nullptr, nullptr, nullptr, D_, F_);
    }

    rmsnorm_kernel<0><<<NT_, 256>>>(h_, out_n, a_, nullptr, nullptr);
    gemm_tc<128, 128, 2, 4, 0><<<gHD, 256>>>(a_, w_out, out, V_, D_);  // logits
    gemm_tc<128, 128, 2, 4, 4><<<gHD, 256>>>(a_, w_ctx, c_,  V_, D_);  // c + softplus

    corr_kernel<<<(S_ + 255) / 256, 256>>>(y);
    ctx_scan_kernel<<<dim3((V_ + 255) / 256, B_, S_ / CTX_CHUNK), 256>>>(out, conv_w);
    nll_kernel<<<NT_, 256>>>(out, y);
    finalize_kernel<<<1, 1>>>(out);
}

// round 11
// speedup vs baseline: 1.1904x; 1.0949x over previous
#include <cuda_runtime.h>
#include <cuda_fp16.h>
#include <math.h>
#include <stdint.h>

#define B_  2
#define S_  512
#define V_  32000
#define D_  768
#define F_  2048
#define L_  4
#define H_  12
#define HD_ 64
#define FCS_ 8
#define YW_ (S_ + FCS_ - 1)   /* 519 */
#define NT_ (B_ * S_)         /* 1024 rows */

// ---------------- static scratch (allocation-free rule) ----------------
__device__ float  g_h [NT_ * D_];
__device__ float  g_q [NT_ * D_];
__device__ float  g_k [NT_ * D_];
__device__ float  g_v [NT_ * D_];
__device__ float  g_g1[NT_ * F_];
__device__ float  g_c [NT_ * V_];          // context head logits c (131 MB)
__device__ float2 g_rope[S_ * 32];
__device__ double g_acc[4];                // [0]=softplus [1]=delta [2]=nll [3]=valid

// fp16 activations (hi + lo residual)
__device__ __align__(16) __half g_ah[NT_ * D_], g_al[NT_ * D_];
__device__ __align__(16) __half g_oh[NT_ * D_], g_ol[NT_ * D_];
__device__ __align__(16) __half g_uh[NT_ * F_], g_ul[NT_ * F_];

// fp16 weights (converted once per launch)
__device__ __align__(16) __half g_wq[L_*D_*D_];
__device__ __align__(16) __half g_wk[L_*D_*D_];
__device__ __align__(16) __half g_wv[L_*D_*D_];
__device__ __align__(16) __half g_wo[L_*D_*D_];
__device__ __align__(16) __half g_w1[L_*F_*D_];
__device__ __align__(16) __half g_w3[L_*F_*D_];
__device__ __align__(16) __half g_w2[L_*D_*F_];
__device__ __align__(16) __half g_wout[V_*D_];
__device__ __align__(16) __half g_wctx[V_*D_];

__device__ __forceinline__ float softplusf(float x) {
    if (x > 15.0f) return x;
    return log1pf(expf(x));
}

__device__ __forceinline__ void mma_f16(float& c0, float& c1, float& c2, float& c3,
                                        uint32_t a0, uint32_t a1, uint32_t a2, uint32_t a3,
                                        uint32_t b0, uint32_t b1) {
    asm volatile("mma.sync.aligned.m16n8k16.row.col.f32.f16.f16.f32 "
                 "{%0,%1,%2,%3}, {%4,%5,%6,%7}, {%8,%9}, {%0,%1,%2,%3};"
                 : "+f"(c0), "+f"(c1), "+f"(c2), "+f"(c3)
                 : "r"(a0), "r"(a1), "r"(a2), "r"(a3), "r"(b0), "r"(b1));
}

__global__ void zero_acc_kernel() {
    if (threadIdx.x < 4) g_acc[threadIdx.x] = 0.0;
}

// ---------------- weight convert fp32 -> fp16 (float4 vectorized) ----------------
__global__ void wconv_kernel(const float* __restrict__ src, __half* __restrict__ dst, int n4) {
    int i = blockIdx.x * blockDim.x + threadIdx.x;
    if (i >= n4) return;
    float4 v = ((const float4*)src)[i];
    ((__half2*)dst)[2 * i]     = __floats2half2_rn(v.x, v.y);
    ((__half2*)dst)[2 * i + 1] = __floats2half2_rn(v.z, v.w);
}

// ---------------- embedding gather ----------------
__global__ void embed_kernel(const int* __restrict__ x, const float* __restrict__ emb) {
    int i = blockIdx.x * blockDim.x + threadIdx.x;
    if (i >= NT_ * D_) return;
    int row = i / D_;
    int d   = i - row * D_;
    g_h[i] = emb[(size_t)x[row] * D_ + d];
}

// ---------------- rmsnorm (SPLIT: 1=fp16 hi only, 2=fp16 hi+lo) ----------------
template<int SPLIT>
__global__ void rmsnorm_kernel(const float* __restrict__ in, const float* __restrict__ w,
                               __half* __restrict__ oh, __half* __restrict__ ol) {
    int row = blockIdx.x;
    const float* ip = in + row * D_;
    __shared__ float red[256];
    float ss = 0.f;
    for (int d = threadIdx.x; d < D_; d += 256) { float v = ip[d]; ss += v * v; }
    red[threadIdx.x] = ss; __syncthreads();
    for (int st = 128; st > 0; st >>= 1) {
        if (threadIdx.x < st) red[threadIdx.x] += red[threadIdx.x + st];
        __syncthreads();
    }
    float rs = rsqrtf(red[0] / (float)D_ + 1e-5f);
    for (int d = threadIdx.x; d < D_; d += 256) {
        float v = ip[d] * rs * w[d];
        __half h = __float2half_rn(v);
        oh[row * D_ + d] = h;
        if (SPLIT == 2) ol[row * D_ + d] = __float2half_rn(v - __half2float(h));
    }
}

#define TLD 20   /* smem row stride (u32): fragment loads conflict-free */

// =======================================================================
//  fp16 NT-GEMM:  C[m,n] (op)= sum_k A[m,k]*W[n,k]
//  NI=1: A=hi only (1 mma/k16).  NI=2: A=hi+lo residual (2 mma/k16,
//  only B rounds).  B is plain fp16.  Fragment layout validated rd8/rd10.
//  EPI: 0=store 1=add 2=silu 3=mulG->fp16 hi/lo 4=store+softplus-sum
// =======================================================================
template<int BM, int BN, int WM, int WN, int EPI, int NI>
__device__ __forceinline__ void gemm_f16_core(const __half* __restrict__ Ah,
                                              const __half* __restrict__ Al,
                                              const __half* __restrict__ Bw,
                                              float* __restrict__ C,
                                              const float* __restrict__ G,
                                              __half* __restrict__ Oh,
                                              __half* __restrict__ Ol,
                                              int N, int K, int bm, int bn) {
    constexpr int THREADS = WM * WN * 32;
    constexpr int WTM = BM / WM;
    constexpr int WTN = BN / WN;
    constexpr int MT  = WTM / 16;
    constexpr int NTT = WTN / 8;
    constexpr int RPP = THREADS / 2;
    constexpr int NLA = BM / RPP;
    constexpr int NLB = BN / RPP;

    __shared__ uint32_t As[2][BM][TLD];
    __shared__ uint32_t Bs[2][BN][TLD];
    __shared__ float sred[THREADS];

    const int tid  = threadIdx.x;
    const int lane = tid & 31;
    const int wid  = tid >> 5;
    const int wm   = wid / WN;
    const int wn   = wid % WN;

    const int lr = tid >> 1;
    const int ks = (tid & 1) * 8;   // element offset 0/8 in k16 chunk
    const int js = ks >> 1;         // u32 pair offset 0/4
    const __half* Agh = Ah + (size_t)(bm + lr) * K + ks;
    const __half* Agl = (NI == 2) ? Al + (size_t)(bm + lr) * K + ks : nullptr;
    const __half* Bg  = Bw + (size_t)(bn + lr) * K + ks;

    float acc[MT][NTT][4];
#pragma unroll
    for (int i = 0; i < MT; i++)
#pragma unroll
        for (int j = 0; j < NTT; j++)
#pragma unroll
            for (int q = 0; q < 4; q++) acc[i][j][q] = 0.f;

    uint4 pah[NLA], pal[NLA], pbh[NLB];

#pragma unroll
    for (int l = 0; l < NLA; l++) {
        pah[l] = *(const uint4*)(Agh + (size_t)l * RPP * K);
        if (NI == 2) pal[l] = *(const uint4*)(Agl + (size_t)l * RPP * K);
    }
#pragma unroll
    for (int l = 0; l < NLB; l++)
        pbh[l] = *(const uint4*)(Bg + (size_t)l * RPP * K);

    auto store_tiles = [&](int buf) {
#pragma unroll
        for (int l = 0; l < NLA; l++) {
            *(uint4*)&As[buf][lr + l * RPP][js] = pah[l];
            if (NI == 2) *(uint4*)&As[buf][lr + l * RPP][8 + js] = pal[l];
        }
#pragma unroll
        for (int l = 0; l < NLB; l++)
            *(uint4*)&Bs[buf][lr + l * RPP][js] = pbh[l];
    };

    store_tiles(0);
    __syncthreads();

    const int nk = K / 16;
    for (int kc = 0; kc < nk; kc++) {
        const int cur = kc & 1;
        if (kc + 1 < nk) {
            const int off = (kc + 1) * 16;
#pragma unroll
            for (int l = 0; l < NLA; l++) {
                pah[l] = *(const uint4*)(Agh + (size_t)l * RPP * K + off);
                if (NI == 2) pal[l] = *(const uint4*)(Agl + (size_t)l * RPP * K + off);
            }
#pragma unroll
            for (int l = 0; l < NLB; l++)
                pbh[l] = *(const uint4*)(Bg + (size_t)l * RPP * K + off);
        }

        {
            const int jq = lane & 3;
            uint32_t ah[MT][4], al[MT][4], bh[NTT][2];
#pragma unroll
            for (int mt = 0; mt < MT; mt++) {
                int row = wm * WTM + mt * 16 + (lane >> 2);
                ah[mt][0] = As[cur][row][jq];
                ah[mt][1] = As[cur][row + 8][jq];
                ah[mt][2] = As[cur][row][jq + 4];
                ah[mt][3] = As[cur][row + 8][jq + 4];
                if (NI == 2) {
                    al[mt][0] = As[cur][row][jq + 8];
                    al[mt][1] = As[cur][row + 8][jq + 8];
                    al[mt][2] = As[cur][row][jq + 12];
                    al[mt][3] = As[cur][row + 8][jq + 12];
                }
            }
#pragma unroll
            for (int nt = 0; nt < NTT; nt++) {
                int nr = wn * WTN + nt * 8 + (lane >> 2);
                bh[nt][0] = Bs[cur][nr][jq];
                bh[nt][1] = Bs[cur][nr][jq + 4];
            }
#pragma unroll
            for (int mt = 0; mt < MT; mt++)
#pragma unroll
                for (int nt = 0; nt < NTT; nt++) {
                    mma_f16(acc[mt][nt][0], acc[mt][nt][1], acc[mt][nt][2], acc[mt][nt][3],
                            ah[mt][0], ah[mt][1], ah[mt][2], ah[mt][3],
                            bh[nt][0], bh[nt][1]);
                    if (NI == 2)
                        mma_f16(acc[mt][nt][0], acc[mt][nt][1], acc[mt][nt][2], acc[mt][nt][3],
                                al[mt][0], al[mt][1], al[mt][2], al[mt][3],
                                bh[nt][0], bh[nt][1]);
                }
        }

        if (kc + 1 < nk) store_tiles(cur ^ 1);
        __syncthreads();
    }

    // ---------------- epilogue ----------------
    float spsum = 0.f;
#pragma unroll
    for (int mt = 0; mt < MT; mt++) {
        int row = bm + wm * WTM + mt * 16 + (lane >> 2);
#pragma unroll
        for (int nt = 0; nt < NTT; nt++) {
            int col = bn + wn * WTN + nt * 8 + (lane & 3) * 2;
            float* a4 = acc[mt][nt];
            size_t i0 = (size_t)row * N + col;
            size_t i1 = (size_t)(row + 8) * N + col;
            float2 r0 = make_float2(a4[0], a4[1]);
            float2 r1 = make_float2(a4[2], a4[3]);
            if (EPI == 1) {
                float2 o0 = *(const float2*)(C + i0);
                float2 o1 = *(const float2*)(C + i1);
                r0.x += o0.x; r0.y += o0.y;
                r1.x += o1.x; r1.y += o1.y;
            } else if (EPI == 2) {
                r0.x = r0.x / (1.f + expf(-r0.x));
                r0.y = r0.y / (1.f + expf(-r0.y));
                r1.x = r1.x / (1.f + expf(-r1.x));
                r1.y = r1.y / (1.f + expf(-r1.y));
            } else if (EPI == 3) {
                float2 g0 = *(const float2*)(G + i0);
                float2 g1v = *(const float2*)(G + i1);
                r0.x *= g0.x; r0.y *= g0.y;
                r1.x *= g1v.x; r1.y *= g1v.y;
            } else if (EPI == 4) {
                spsum += softplusf(r0.x) + softplusf(r0.y) +
                         softplusf(r1.x) + softplusf(r1.y);
            }
            if (EPI == 3) {
                __half2 h0 = __floats2half2_rn(r0.x, r0.y);
                __half2 h1 = __floats2half2_rn(r1.x, r1.y);
                __half2 l0 = __floats2half2_rn(r0.x - __half2float(__low2half(h0)),
                                               r0.y - __half2float(__high2half(h0)));
                __half2 l1 = __floats2half2_rn(r1.x - __half2float(__low2half(h1)),
                                               r1.y - __half2float(__high2half(h1)));
                *(__half2*)(Oh + i0) = h0;
                *(__half2*)(Oh + i1) = h1;
                *(__half2*)(Ol + i0) = l0;
                *(__half2*)(Ol + i1) = l1;
            } else {
                *(float2*)(C + i0) = r0;
                *(float2*)(C + i1) = r1;
            }
        }
    }
    if (EPI == 4) {
        sred[tid] = spsum; __syncthreads();
        for (int st = THREADS / 2; st > 0; st >>= 1) {
            if (tid < st) sred[tid] += sred[tid + st];
            __syncthreads();
        }
        if (tid == 0) atomicAdd(&g_acc[0], (double)sred[0]);
    }
}

template<int BM, int BN, int WM, int WN, int EPI, int NI>
__global__ __launch_bounds__(WM * WN * 32)
void gemm_f16(const __half* __restrict__ Ah, const __half* __restrict__ Al,
              const __half* __restrict__ Bw,
              float* __restrict__ C, const float* __restrict__ G,
              __half* __restrict__ Oh, __half* __restrict__ Ol, int N, int K) {
    gemm_f16_core<BM, BN, WM, WN, EPI, NI>(Ah, Al, Bw, C, G, Oh, Ol, N, K,
                                           blockIdx.x * BM, blockIdx.y * BN);
}

// fused q/k/v (blockIdx.z selects weight/output), A-split fp16
__global__ __launch_bounds__(128)
void gemm_qkv_f16(const __half* __restrict__ Ah, const __half* __restrict__ Al,
                  int layer_off,
                  float* __restrict__ C0, float* __restrict__ C1, float* __restrict__ C2,
                  int N, int K) {
    const __half* Bz; float* Cz;
    if (blockIdx.z == 0)      { Bz = g_wq + layer_off; Cz = C0; }
    else if (blockIdx.z == 1) { Bz = g_wk + layer_off; Cz = C1; }
    else                      { Bz = g_wv + layer_off; Cz = C2; }
    gemm_f16_core<64, 64, 2, 2, 0, 2>(Ah, Al, Bz, Cz, nullptr, nullptr, nullptr,
                                      N, K, blockIdx.x * 64, blockIdx.y * 64);
}

// ---------------- RoPE ----------------
__global__ void rope_table_kernel() {
    int i = blockIdx.x * blockDim.x + threadIdx.x;
    if (i >= S_ * 32) return;
    int s = i / 32, p = i - (i / 32) * 32;
    float f   = expf((float)(2 * p) * (-logf(10000.0f) / (float)HD_));
    float ang = (float)s * f;
    double a  = (double)ang;
    g_rope[i] = make_float2((float)cos(a), (float)sin(a));
}

__global__ void rope_apply_kernel() {
    int idx = blockIdx.x * blockDim.x + threadIdx.x;          // over B*S*H*32
    if (idx >= B_ * S_ * H_ * 32) return;
    int p = idx & 31;
    int h = (idx >> 5) % H_;
    int s = (idx / (32 * H_)) % S_;
    int b = idx / (32 * H_ * S_);
    float2 cs = g_rope[s * 32 + p];
    int base = ((b * S_ + s) * D_) + h * HD_ + 2 * p;
    float xr, xi;
    xr = g_q[base]; xi = g_q[base + 1];
    g_q[base]     = xr * cs.x - xi * cs.y;
    g_q[base + 1] = xr * cs.y + xi * cs.x;
    xr = g_k[base]; xi = g_k[base + 1];
    g_k[base]     = xr * cs.x - xi * cs.y;
    g_k[base + 1] = xr * cs.y + xi * cs.x;
}

// ---------------- flash-style attention (writes o as fp16 hi+lo) ----------------
__global__ __launch_bounds__(256)
void attn_flash() {
    const int qt = blockIdx.x;
    const int bh = blockIdx.y;
    const int b = bh / H_, h = bh - (bh / H_) * H_;
    const int tid = threadIdx.x;
    const int q  = tid >> 2;
    const int dg = (tid & 3) * 16;
    const int q0 = qt * 64;

    __shared__ float KS[64][68];
    __shared__ float Vs[64][68];
    __shared__ float rowm[64], rows[64], cfs[64];

    float4 qr[16];
    const float* qp = g_q + ((size_t)(b * S_ + q0 + q)) * D_ + h * HD_;
#pragma unroll
    for (int j = 0; j < 16; j++) qr[j] = *(const float4*)(qp + 4 * j);

    float acc[16];
#pragma unroll
    for (int j = 0; j < 16; j++) acc[j] = 0.f;
    if (tid < 64) { rowm[tid] = -1e30f; rows[tid] = 0.f; }

    for (int k0 = 0; k0 <= q0; k0 += 64) {
        {
            int r = tid >> 2, c = (tid & 3) * 16;
            const float* kp = g_k + ((size_t)(b * S_ + k0 + r)) * D_ + h * HD_ + c;
            const float* vp = g_v + ((size_t)(b * S_ + k0 + r)) * D_ + h * HD_ + c;
#pragma unroll
            for (int j = 0; j < 4; j++) {
                *(float4*)&KS[r][c + 4 * j] = *(const float4*)(kp + 4 * j);
                *(float4*)&Vs[r][c + 4 * j] = *(const float4*)(vp + 4 * j);
            }
        }
        __syncthreads();

        float sreg[16];
        {
            const int kb = (tid & 3) * 16;
#pragma unroll
            for (int j = 0; j < 16; j++) {
                int kk = kb + j;
                float d = 0.f;
#pragma unroll
                for (int t4 = 0; t4 < 16; t4++) {
                    float4 kv = *(const float4*)&KS[kk][4 * t4];
                    d += qr[t4].x * kv.x + qr[t4].y * kv.y +
                         qr[t4].z * kv.z + qr[t4].w * kv.w;
                }
                sreg[j] = (k0 + kk <= q0 + q) ? d * 0.125f : -1e30f;
            }
        }
        __syncthreads();

        {
            const int kb = (tid & 3) * 16;
#pragma unroll
            for (int j = 0; j < 16; j++) KS[q][kb + j] = sreg[j];
        }
        __syncthreads();

        if (tid < 64) {
            float mo = rowm[tid];
            float tm = mo;
#pragma unroll 8
            for (int kk = 0; kk < 64; kk++) tm = fmaxf(tm, KS[tid][kk]);
            float cf = expf(mo - tm);
            float ps = 0.f;
#pragma unroll 8
            for (int kk = 0; kk < 64; kk++) {
                float p = expf(KS[tid][kk] - tm);
                KS[tid][kk] = p;
                ps += p;
            }
            rowm[tid] = tm;
            rows[tid] = rows[tid] * cf + ps;
            cfs[tid] = cf;
        }
        __syncthreads();

        {
            float cf = cfs[q];
#pragma unroll
            for (int j = 0; j < 16; j++) acc[j] *= cf;
            for (int kk = 0; kk < 64; kk++) {
                float p = KS[q][kk];
#pragma unroll
                for (int j4 = 0; j4 < 4; j4++) {
                    float4 vv = *(const float4*)&Vs[kk][dg + 4 * j4];
                    acc[4 * j4 + 0] += p * vv.x;
                    acc[4 * j4 + 1] += p * vv.y;
                    acc[4 * j4 + 2] += p * vv.z;
                    acc[4 * j4 + 3] += p * vv.w;
                }
            }
        }
        __syncthreads();
    }

    float inv = 1.f / rows[q];
    size_t base = ((size_t)(b * S_ + q0 + q)) * D_ + h * HD_ + dg;
#pragma unroll
    for (int j2 = 0; j2 < 8; j2++) {
        float v0 = acc[2 * j2] * inv, v1 = acc[2 * j2 + 1] * inv;
        __half2 hh = __floats2half2_rn(v0, v1);
        __half2 ll = __floats2half2_rn(v0 - __half2float(__low2half(hh)),
                                       v1 - __half2float(__high2half(hh)));
        *(__half2*)(g_oh + base + 2 * j2) = hh;
        *(__half2*)(g_ol + base + 2 * j2) = ll;
    }
}

// ---------------- sparse BCE correction ----------------
__global__ void corr_kernel(const int* __restrict__ y) {
    int s = blockIdx.x * blockDim.x + threadIdx.x;
    if (s >= S_) return;
    int tok[2][FCS_];
    for (int b = 0; b < 2; b++)
        for (int j = 0; j < FCS_; j++)
            tok[b][j] = y[b * YW_ + (FCS_ - 1) + ((s - (FCS_ - 1) + j + S_) & (S_ - 1))];
    double dsum = 0.0;
    for (int b = 0; b < 2; b++)
        for (int j = 0; j < FCS_; j++) {
            int v = tok[b][j];
            bool first = true;
            for (int b2 = 0; b2 <= b && first; b2++) {
                int jmax = (b2 == b) ? j : FCS_;
                for (int j2 = 0; j2 < jmax; j2++)
                    if (tok[b2][j2] == v) { first = false; break; }
            }
            if (!first) continue;
            int c0 = 0, c1 = 0;
            for (int j2 = 0; j2 < FCS_; j2++) {
                c0 += (tok[0][j2] == v);
                c1 += (tok[1][j2] == v);
            }
            float w = (c0 > 1 || c1 > 1) ? 1.5f : 1.0f;
            for (int b2 = 0; b2 < 2; b2++) {
                float cv = g_c[((size_t)(b2 * S_ + s)) * V_ + v];
                float t  = ((b2 == 0 ? c0 : c1) > 0) ? 1.f : 0.f;
                dsum += (double)((w - 1.f) * softplusf(cv) - w * t * cv);
            }
        }
    atomicAdd(&g_acc[1], dsum);
}

// ---------------- logits += exp-kernel context (ring-buffer window) ----
#define CTX_CHUNK 128
__global__ void ctx_scan_kernel(float* __restrict__ logits, const float* __restrict__ conv_w) {
    int v = blockIdx.x * blockDim.x + threadIdx.x;
    if (v >= V_) return;
    int b  = blockIdx.y;
    int s0 = blockIdx.z * CTX_CHUNK;
    float e = expf(-conv_w[0]);

    float pw[FCS_];
    pw[FCS_ - 1] = 1.f;
#pragma unroll
    for (int d = FCS_ - 1; d >= 1; --d) pw[d - 1] = pw[d] * e;

    float ring[FCS_];
#pragma unroll
    for (int j = 1; j <= FCS_; j++) {
        int sp = s0 - j;
        ring[(8 - j) & 7] = (sp >= 0) ? g_c[((size_t)(b * S_ + sp)) * V_ + v] : 0.f;
    }

    for (int t = 0; t < CTX_CHUNK / 8; t++) {
#pragma unroll
        for (int u = 0; u < 8; u++) {
            int s = s0 + 8 * t + u;
            size_t idx = ((size_t)(b * S_ + s)) * V_ + v;
            float ctx = 0.f;
#pragma unroll
            for (int d = 1; d <= FCS_; d++)
                ctx += pw[d - 1] * ring[(u - d) & 7];
            logits[idx] += ctx;
            ring[u] = g_c[idx];
        }
    }
}

// ---------------- NLL ----------------
__global__ void nll_kernel(const float* __restrict__ logits, const int* __restrict__ y) {
    int row = blockIdx.x;
    int b = row / S_, s = row - (row / S_) * S_;
    const float* lp = logits + (size_t)row * V_;
    __shared__ float red[256];
    float m = -1e30f;
    for (int v = threadIdx.x; v < V_; v += 256) m = fmaxf(m, lp[v]);
    red[threadIdx.x] = m; __syncthreads();
    for (int st = 128; st > 0; st >>= 1) {
        if (threadIdx.x < st) red[threadIdx.x] = fmaxf(red[threadIdx.x], red[threadIdx.x + st]);
        __syncthreads();
    }
    m = red[0];
    __syncthreads();
    float ssum = 0.f;
    for (int v = threadIdx.x; v < V_; v += 256) ssum += expf(lp[v] - m);
    red[threadIdx.x] = ssum; __syncthreads();
    for (int st = 128; st > 0; st >>= 1) {
        if (threadIdx.x < st) red[threadIdx.x] += red[threadIdx.x + st];
        __syncthreads();
    }
    if (threadIdx.x == 0) {
        int yt = y[b * YW_ + s];
        if (yt != -1) {
            float lse = m + logf(red[0]);
            atomicAdd(&g_acc[2], (double)(lse - lp[yt]));
            atomicAdd(&g_acc[3], 1.0);
        }
    }
}

__global__ void finalize_kernel(float* __restrict__ out) {
    double cnt = g_acc[3] < 1.0 ? 1.0 : g_acc[3];
    out[(size_t)NT_ * V_]     = (float)(g_acc[2] / cnt);
    out[(size_t)NT_ * V_ + 1] = (float)((g_acc[0] + g_acc[1]) / ((double)NT_ * (double)V_));
}

// ---------------- launcher ----------------
extern "C" void kernel_launch(void* const* d_in, const int* in_sizes, int n_in,
                              void* d_out, int out_size) {
    const int*   x      = (const int*)  d_in[0];
    const int*   y      = (const int*)  d_in[1];
    const float* emb    = (const float*)d_in[2];
    const float* wq     = (const float*)d_in[3];
    const float* wk     = (const float*)d_in[4];
    const float* wv     = (const float*)d_in[5];
    const float* wo     = (const float*)d_in[6];
    const float* w1     = (const float*)d_in[7];
    const float* w2     = (const float*)d_in[8];
    const float* w3     = (const float*)d_in[9];
    const float* attn_n = (const float*)d_in[10];
    const float* ffn_n  = (const float*)d_in[11];
    const float* out_n  = (const float*)d_in[12];
    const float* w_out  = (const float*)d_in[13];
    const float* w_ctx  = (const float*)d_in[14];
    const float* conv_w = (const float*)d_in[15];
    float* out = (float*)d_out;

    float *h_, *q_, *k_, *v_, *g1_, *c_;
    __half *ah_, *al_, *oh_, *ol_, *uh_, *ul_;
    __half *wq_f, *wk_f, *wv_f, *wo_f, *w1_f, *w3_f, *w2_f, *wout_f, *wctx_f;
    cudaGetSymbolAddress((void**)&h_,  g_h);
    cudaGetSymbolAddress((void**)&q_,  g_q);
    cudaGetSymbolAddress((void**)&k_,  g_k);
    cudaGetSymbolAddress((void**)&v_,  g_v);
    cudaGetSymbolAddress((void**)&g1_, g_g1);
    cudaGetSymbolAddress((void**)&c_,  g_c);
    cudaGetSymbolAddress((void**)&ah_, g_ah);
    cudaGetSymbolAddress((void**)&al_, g_al);
    cudaGetSymbolAddress((void**)&oh_, g_oh);
    cudaGetSymbolAddress((void**)&ol_, g_ol);
    cudaGetSymbolAddress((void**)&uh_, g_uh);
    cudaGetSymbolAddress((void**)&ul_, g_ul);
    cudaGetSymbolAddress((void**)&wq_f, g_wq);
    cudaGetSymbolAddress((void**)&wk_f, g_wk);
    cudaGetSymbolAddress((void**)&wv_f, g_wv);
    cudaGetSymbolAddress((void**)&wo_f, g_wo);
    cudaGetSymbolAddress((void**)&w1_f, g_w1);
    cudaGetSymbolAddress((void**)&w3_f, g_w3);
    cudaGetSymbolAddress((void**)&w2_f, g_w2);
    cudaGetSymbolAddress((void**)&wout_f, g_wout);
    cudaGetSymbolAddress((void**)&wctx_f, g_wctx);

    zero_acc_kernel<<<1, 32>>>();
    embed_kernel<<<(NT_ * D_ + 255) / 256, 256>>>(x, emb);
    rope_table_kernel<<<(S_ * 32 + 255) / 256, 256>>>();

    // weight converts (fp32 -> fp16, whole tensors)
    {
        int nDD4 = L_ * D_ * D_ / 4;
        int nFD4 = L_ * F_ * D_ / 4;
        int nVD4 = V_ * D_ / 4;
        wconv_kernel<<<(nDD4 + 255) / 256, 256>>>(wq, wq_f, nDD4);
        wconv_kernel<<<(nDD4 + 255) / 256, 256>>>(wk, wk_f, nDD4);
        wconv_kernel<<<(nDD4 + 255) / 256, 256>>>(wv, wv_f, nDD4);
        wconv_kernel<<<(nDD4 + 255) / 256, 256>>>(wo, wo_f, nDD4);
        wconv_kernel<<<(nFD4 + 255) / 256, 256>>>(w1, w1_f, nFD4);
        wconv_kernel<<<(nFD4 + 255) / 256, 256>>>(w3, w3_f, nFD4);
        wconv_kernel<<<(nFD4 + 255) / 256, 256>>>(w2, w2_f, nFD4);
        wconv_kernel<<<(nVD4 + 255) / 256, 256>>>(w_out, wout_f, nVD4);
        wconv_kernel<<<(nVD4 + 255) / 256, 256>>>(w_ctx, wctx_f, nVD4);
    }

    dim3 gQKV(NT_ / 64, D_ / 64, 3);     // 16 x 12 x 3 (64x64 tiles)
    dim3 gDs (NT_ / 64, D_ / 64);        // 16 x 12
    dim3 gF  (NT_ / 128, F_ / 64);       // 8 x 32 (128x64 tiles)
    dim3 gHD (NT_ / 128, V_ / 128);      // 8 x 250 (m fast for L2 weight reuse)

    for (int i = 0; i < L_; i++) {
        int offDD = i * D_ * D_;
        int offFD = i * F_ * D_;

        // attn path: A-split fp16 (2 mma/k16; only weights round)
        rmsnorm_kernel<2><<<NT_, 256>>>(h_, attn_n + i * D_, ah_, al_);
        gemm_qkv_f16<<<gQKV, 128>>>(ah_, al_, offDD, q_, k_, v_, D_, D_);
        rope_apply_kernel<<<(B_ * S_ * H_ * 32 + 255) / 256, 256>>>();
        attn_flash<<<dim3(S_ / 64, B_ * H_), 256>>>();
        gemm_f16<64, 64, 2, 2, 1, 2><<<gDs, 128>>>(oh_, ol_, wo_f + offDD,
                                                   h_, nullptr, nullptr, nullptr, D_, D_);

        // ffn path: A-split fp16 (2 mma/k16; only weights round)
        rmsnorm_kernel<2><<<NT_, 256>>>(h_, ffn_n + i * D_, ah_, al_);
        gemm_f16<128, 64, 2, 2, 2, 2><<<gF, 128>>>(ah_, al_, w1_f + offFD,
                                                   g1_, nullptr, nullptr, nullptr, F_, D_);
        gemm_f16<128, 64, 2, 2, 3, 2><<<gF, 128>>>(ah_, al_, w3_f + offFD,
                                                   nullptr, g1_, uh_, ul_, F_, D_);
        gemm_f16<64, 64, 2, 2, 1, 2><<<gDs, 128>>>(uh_, ul_, w2_f + offFD,
                                                   h_, nullptr, nullptr, nullptr, D_, F_);
    }

    // heads: plain fp16 (1 mma/k16; same 11-bit mantissa as tf32, half the instrs)
    rmsnorm_kernel<1><<<NT_, 256>>>(h_, out_n, ah_, nullptr);
    gemm_f16<128, 128, 2, 4, 0, 1><<<gHD, 256>>>(ah_, nullptr, wout_f,
                                                 out, nullptr, nullptr, nullptr, V_, D_);
    gemm_f16<128, 128, 2, 4, 4, 1><<<gHD, 256>>>(ah_, nullptr, wctx_f,
                                                 c_, nullptr, nullptr, nullptr, V_, D_);

    corr_kernel<<<(S_ + 255) / 256, 256>>>(y);
    ctx_scan_kernel<<<dim3((V_ + 255) / 256, B_, S_ / CTX_CHUNK), 256>>>(out, conv_w);
    nll_kernel<<<NT_, 256>>>(out, y);
    finalize_kernel<<<1, 1>>>(out);
}

// round 12
// speedup vs baseline: 1.2288x; 1.0323x over previous
#include <cuda_runtime.h>
#include <cuda_fp16.h>
#include <math.h>
#include <stdint.h>

#define B_  2
#define S_  512
#define V_  32000
#define D_  768
#define F_  2048
#define L_  4
#define H_  12
#define HD_ 64
#define FCS_ 8
#define YW_ (S_ + FCS_ - 1)   /* 519 */
#define NT_ (B_ * S_)         /* 1024 rows */

// ---------------- static scratch (allocation-free rule) ----------------
__device__ float  g_h [NT_ * D_];
__device__ float  g_q [NT_ * D_];
__device__ float  g_k [NT_ * D_];
__device__ float  g_v [NT_ * D_];
__device__ float  g_g1[NT_ * F_];
__device__ float  g_c [NT_ * V_];          // context head logits c (131 MB)
__device__ float2 g_rope[S_ * 32];
__device__ double g_acc[4];                // [0]=softplus [1]=delta [2]=nll [3]=valid

// fp16 activations (hi + lo residual where needed)
__device__ __align__(16) __half g_ah[NT_ * D_], g_al[NT_ * D_];
__device__ __align__(16) __half g_oh[NT_ * D_];
__device__ __align__(16) __half g_uh[NT_ * F_], g_ul[NT_ * F_];

// fp16 weights (converted once per launch)
__device__ __align__(16) __half g_wq[L_*D_*D_];
__device__ __align__(16) __half g_wk[L_*D_*D_];
__device__ __align__(16) __half g_wv[L_*D_*D_];
__device__ __align__(16) __half g_wo[L_*D_*D_];
__device__ __align__(16) __half g_w1[L_*F_*D_];
__device__ __align__(16) __half g_w3[L_*F_*D_];
__device__ __align__(16) __half g_w2[L_*D_*F_];
__device__ __align__(16) __half g_wout[V_*D_];
__device__ __align__(16) __half g_wctx[V_*D_];

__device__ __forceinline__ float softplusf(float x) {
    if (x > 15.0f) return x;
    return log1pf(expf(x));
}

__device__ __forceinline__ void mma_f16(float& c0, float& c1, float& c2, float& c3,
                                        uint32_t a0, uint32_t a1, uint32_t a2, uint32_t a3,
                                        uint32_t b0, uint32_t b1) {
    asm volatile("mma.sync.aligned.m16n8k16.row.col.f32.f16.f16.f32 "
                 "{%0,%1,%2,%3}, {%4,%5,%6,%7}, {%8,%9}, {%0,%1,%2,%3};"
                 : "+f"(c0), "+f"(c1), "+f"(c2), "+f"(c3)
                 : "r"(a0), "r"(a1), "r"(a2), "r"(a3), "r"(b0), "r"(b1));
}

__global__ void zero_acc_kernel() {
    if (threadIdx.x < 4) g_acc[threadIdx.x] = 0.0;
}

// ---------------- weight convert fp32 -> fp16 (float4 vectorized) ----------------
__global__ void wconv_kernel(const float* __restrict__ src, __half* __restrict__ dst, int n4) {
    int i = blockIdx.x * blockDim.x + threadIdx.x;
    if (i >= n4) return;
    float4 v = ((const float4*)src)[i];
    ((__half2*)dst)[2 * i]     = __floats2half2_rn(v.x, v.y);
    ((__half2*)dst)[2 * i + 1] = __floats2half2_rn(v.z, v.w);
}

// ---------------- embedding gather ----------------
__global__ void embed_kernel(const int* __restrict__ x, const float* __restrict__ emb) {
    int i = blockIdx.x * blockDim.x + threadIdx.x;
    if (i >= NT_ * D_) return;
    int row = i / D_;
    int d   = i - row * D_;
    g_h[i] = emb[(size_t)x[row] * D_ + d];
}

// ---------------- rmsnorm (SPLIT: 1=fp16 hi only, 2=fp16 hi+lo) ----------------
template<int SPLIT>
__global__ void rmsnorm_kernel(const float* __restrict__ in, const float* __restrict__ w,
                               __half* __restrict__ oh, __half* __restrict__ ol) {
    int row = blockIdx.x;
    const float* ip = in + row * D_;
    __shared__ float red[256];
    float ss = 0.f;
    for (int d = threadIdx.x; d < D_; d += 256) { float v = ip[d]; ss += v * v; }
    red[threadIdx.x] = ss; __syncthreads();
    for (int st = 128; st > 0; st >>= 1) {
        if (threadIdx.x < st) red[threadIdx.x] += red[threadIdx.x + st];
        __syncthreads();
    }
    float rs = rsqrtf(red[0] / (float)D_ + 1e-5f);
    for (int d = threadIdx.x; d < D_; d += 256) {
        float v = ip[d] * rs * w[d];
        __half h = __float2half_rn(v);
        oh[row * D_ + d] = h;
        if (SPLIT == 2) ol[row * D_ + d] = __float2half_rn(v - __half2float(h));
    }
}

#define TLD 20   /* smem row stride (u32): fragment loads conflict-free */

// =======================================================================
//  fp16 NT-GEMM:  C[m,n] (op)= sum_k A[m,k]*W[n,k]
//  NI=1: A=hi only (1 mma/k16).  NI=2: A=hi+lo residual (2 mma/k16,
//  only B rounds).  B is plain fp16.  Fragment layout validated rd8/rd10.
//  EPI: 0=store 1=add 2=silu 3=mulG->fp16 hi/lo 4=store+softplus-sum
// =======================================================================
template<int BM, int BN, int WM, int WN, int EPI, int NI>
__device__ __forceinline__ void gemm_f16_core(const __half* __restrict__ Ah,
                                              const __half* __restrict__ Al,
                                              const __half* __restrict__ Bw,
                                              float* __restrict__ C,
                                              const float* __restrict__ G,
                                              __half* __restrict__ Oh,
                                              __half* __restrict__ Ol,
                                              int N, int K, int bm, int bn) {
    constexpr int THREADS = WM * WN * 32;
    constexpr int WTM = BM / WM;
    constexpr int WTN = BN / WN;
    constexpr int MT  = WTM / 16;
    constexpr int NTT = WTN / 8;
    constexpr int RPP = THREADS / 2;
    constexpr int NLA = BM / RPP;
    constexpr int NLB = BN / RPP;

    __shared__ uint32_t As[2][BM][TLD];
    __shared__ uint32_t Bs[2][BN][TLD];
    __shared__ float sred[THREADS];

    const int tid  = threadIdx.x;
    const int lane = tid & 31;
    const int wid  = tid >> 5;
    const int wm   = wid / WN;
    const int wn   = wid % WN;

    const int lr = tid >> 1;
    const int ks = (tid & 1) * 8;   // element offset 0/8 in k16 chunk
    const int js = ks >> 1;         // u32 pair offset 0/4
    const __half* Agh = Ah + (size_t)(bm + lr) * K + ks;
    const __half* Agl = (NI == 2) ? Al + (size_t)(bm + lr) * K + ks : nullptr;
    const __half* Bg  = Bw + (size_t)(bn + lr) * K + ks;

    float acc[MT][NTT][4];
#pragma unroll
    for (int i = 0; i < MT; i++)
#pragma unroll
        for (int j = 0; j < NTT; j++)
#pragma unroll
            for (int q = 0; q < 4; q++) acc[i][j][q] = 0.f;

    uint4 pah[NLA], pal[NLA], pbh[NLB];

#pragma unroll
    for (int l = 0; l < NLA; l++) {
        pah[l] = *(const uint4*)(Agh + (size_t)l * RPP * K);
        if (NI == 2) pal[l] = *(const uint4*)(Agl + (size_t)l * RPP * K);
    }
#pragma unroll
    for (int l = 0; l < NLB; l++)
        pbh[l] = *(const uint4*)(Bg + (size_t)l * RPP * K);

    auto store_tiles = [&](int buf) {
#pragma unroll
        for (int l = 0; l < NLA; l++) {
            *(uint4*)&As[buf][lr + l * RPP][js] = pah[l];
            if (NI == 2) *(uint4*)&As[buf][lr + l * RPP][8 + js] = pal[l];
        }
#pragma unroll
        for (int l = 0; l < NLB; l++)
            *(uint4*)&Bs[buf][lr + l * RPP][js] = pbh[l];
    };

    store_tiles(0);
    __syncthreads();

    const int nk = K / 16;
    for (int kc = 0; kc < nk; kc++) {
        const int cur = kc & 1;
        if (kc + 1 < nk) {
            const int off = (kc + 1) * 16;
#pragma unroll
            for (int l = 0; l < NLA; l++) {
                pah[l] = *(const uint4*)(Agh + (size_t)l * RPP * K + off);
                if (NI == 2) pal[l] = *(const uint4*)(Agl + (size_t)l * RPP * K + off);
            }
#pragma unroll
            for (int l = 0; l < NLB; l++)
                pbh[l] = *(const uint4*)(Bg + (size_t)l * RPP * K + off);
        }

        {
            const int jq = lane & 3;
            uint32_t ah[MT][4], al[MT][4], bh[NTT][2];
#pragma unroll
            for (int mt = 0; mt < MT; mt++) {
                int row = wm * WTM + mt * 16 + (lane >> 2);
                ah[mt][0] = As[cur][row][jq];
                ah[mt][1] = As[cur][row + 8][jq];
                ah[mt][2] = As[cur][row][jq + 4];
                ah[mt][3] = As[cur][row + 8][jq + 4];
                if (NI == 2) {
                    al[mt][0] = As[cur][row][jq + 8];
                    al[mt][1] = As[cur][row + 8][jq + 8];
                    al[mt][2] = As[cur][row][jq + 12];
                    al[mt][3] = As[cur][row + 8][jq + 12];
                }
            }
#pragma unroll
            for (int nt = 0; nt < NTT; nt++) {
                int nr = wn * WTN + nt * 8 + (lane >> 2);
                bh[nt][0] = Bs[cur][nr][jq];
                bh[nt][1] = Bs[cur][nr][jq + 4];
            }
#pragma unroll
            for (int mt = 0; mt < MT; mt++)
#pragma unroll
                for (int nt = 0; nt < NTT; nt++) {
                    mma_f16(acc[mt][nt][0], acc[mt][nt][1], acc[mt][nt][2], acc[mt][nt][3],
                            ah[mt][0], ah[mt][1], ah[mt][2], ah[mt][3],
                            bh[nt][0], bh[nt][1]);
                    if (NI == 2)
                        mma_f16(acc[mt][nt][0], acc[mt][nt][1], acc[mt][nt][2], acc[mt][nt][3],
                                al[mt][0], al[mt][1], al[mt][2], al[mt][3],
                                bh[nt][0], bh[nt][1]);
                }
        }

        if (kc + 1 < nk) store_tiles(cur ^ 1);
        __syncthreads();
    }

    // ---------------- epilogue ----------------
    float spsum = 0.f;
#pragma unroll
    for (int mt = 0; mt < MT; mt++) {
        int row = bm + wm * WTM + mt * 16 + (lane >> 2);
#pragma unroll
        for (int nt = 0; nt < NTT; nt++) {
            int col = bn + wn * WTN + nt * 8 + (lane & 3) * 2;
            float* a4 = acc[mt][nt];
            size_t i0 = (size_t)row * N + col;
            size_t i1 = (size_t)(row + 8) * N + col;
            float2 r0 = make_float2(a4[0], a4[1]);
            float2 r1 = make_float2(a4[2], a4[3]);
            if (EPI == 1) {
                float2 o0 = *(const float2*)(C + i0);
                float2 o1 = *(const float2*)(C + i1);
                r0.x += o0.x; r0.y += o0.y;
                r1.x += o1.x; r1.y += o1.y;
            } else if (EPI == 2) {
                r0.x = r0.x / (1.f + expf(-r0.x));
                r0.y = r0.y / (1.f + expf(-r0.y));
                r1.x = r1.x / (1.f + expf(-r1.x));
                r1.y = r1.y / (1.f + expf(-r1.y));
            } else if (EPI == 3) {
                float2 g0 = *(const float2*)(G + i0);
                float2 g1v = *(const float2*)(G + i1);
                r0.x *= g0.x; r0.y *= g0.y;
                r1.x *= g1v.x; r1.y *= g1v.y;
            } else if (EPI == 4) {
                spsum += softplusf(r0.x) + softplusf(r0.y) +
                         softplusf(r1.x) + softplusf(r1.y);
            }
            if (EPI == 3) {
                __half2 h0 = __floats2half2_rn(r0.x, r0.y);
                __half2 h1 = __floats2half2_rn(r1.x, r1.y);
                __half2 l0 = __floats2half2_rn(r0.x - __half2float(__low2half(h0)),
                                               r0.y - __half2float(__high2half(h0)));
                __half2 l1 = __floats2half2_rn(r1.x - __half2float(__low2half(h1)),
                                               r1.y - __half2float(__high2half(h1)));
                *(__half2*)(Oh + i0) = h0;
                *(__half2*)(Oh + i1) = h1;
                *(__half2*)(Ol + i0) = l0;
                *(__half2*)(Ol + i1) = l1;
            } else {
                *(float2*)(C + i0) = r0;
                *(float2*)(C + i1) = r1;
            }
        }
    }
    if (EPI == 4) {
        sred[tid] = spsum; __syncthreads();
        for (int st = THREADS / 2; st > 0; st >>= 1) {
            if (tid < st) sred[tid] += sred[tid + st];
            __syncthreads();
        }
        if (tid == 0) atomicAdd(&g_acc[0], (double)sred[0]);
    }
}

template<int BM, int BN, int WM, int WN, int EPI, int NI>
__global__ __launch_bounds__(WM * WN * 32)
void gemm_f16(const __half* __restrict__ Ah, const __half* __restrict__ Al,
              const __half* __restrict__ Bw,
              float* __restrict__ C, const float* __restrict__ G,
              __half* __restrict__ Oh, __half* __restrict__ Ol, int N, int K) {
    gemm_f16_core<BM, BN, WM, WN, EPI, NI>(Ah, Al, Bw, C, G, Oh, Ol, N, K,
                                           blockIdx.x * BM, blockIdx.y * BN);
}

// fused q/k/v (blockIdx.z selects weight/output), plain fp16 (NI=1)
__global__ __launch_bounds__(128)
void gemm_qkv_f16(const __half* __restrict__ Ah, int layer_off,
                  float* __restrict__ C0, float* __restrict__ C1, float* __restrict__ C2,
                  int N, int K) {
    const __half* Bz; float* Cz;
    if (blockIdx.z == 0)      { Bz = g_wq + layer_off; Cz = C0; }
    else if (blockIdx.z == 1) { Bz = g_wk + layer_off; Cz = C1; }
    else                      { Bz = g_wv + layer_off; Cz = C2; }
    gemm_f16_core<64, 64, 2, 2, 0, 1>(Ah, nullptr, Bz, Cz, nullptr, nullptr, nullptr,
                                      N, K, blockIdx.x * 64, blockIdx.y * 64);
}

// fused heads: z=0 -> logits (EPI0, w_out); z=1 -> c + softplus (EPI4, w_ctx)
__global__ __launch_bounds__(256)
void gemm_heads_f16(const __half* __restrict__ Ah,
                    float* __restrict__ Cout, float* __restrict__ Cc) {
    if (blockIdx.z == 0)
        gemm_f16_core<128, 128, 2, 4, 0, 1>(Ah, nullptr, g_wout, Cout, nullptr,
                                            nullptr, nullptr, V_, D_,
                                            blockIdx.x * 128, blockIdx.y * 128);
    else
        gemm_f16_core<128, 128, 2, 4, 4, 1>(Ah, nullptr, g_wctx, Cc, nullptr,
                                            nullptr, nullptr, V_, D_,
                                            blockIdx.x * 128, blockIdx.y * 128);
}

// ---------------- RoPE ----------------
__global__ void rope_table_kernel() {
    int i = blockIdx.x * blockDim.x + threadIdx.x;
    if (i >= S_ * 32) return;
    int s = i / 32, p = i - (i / 32) * 32;
    float f   = expf((float)(2 * p) * (-logf(10000.0f) / (float)HD_));
    float ang = (float)s * f;
    double a  = (double)ang;
    g_rope[i] = make_float2((float)cos(a), (float)sin(a));
}

__global__ void rope_apply_kernel() {
    int idx = blockIdx.x * blockDim.x + threadIdx.x;          // over B*S*H*32
    if (idx >= B_ * S_ * H_ * 32) return;
    int p = idx & 31;
    int h = (idx >> 5) % H_;
    int s = (idx / (32 * H_)) % S_;
    int b = idx / (32 * H_ * S_);
    float2 cs = g_rope[s * 32 + p];
    int base = ((b * S_ + s) * D_) + h * HD_ + 2 * p;
    float xr, xi;
    xr = g_q[base]; xi = g_q[base + 1];
    g_q[base]     = xr * cs.x - xi * cs.y;
    g_q[base + 1] = xr * cs.y + xi * cs.x;
    xr = g_k[base]; xi = g_k[base + 1];
    g_k[base]     = xr * cs.x - xi * cs.y;
    g_k[base + 1] = xr * cs.y + xi * cs.x;
}

// ---------------- flash-style attention (writes o as fp16 hi) ----------------
__global__ __launch_bounds__(256)
void attn_flash() {
    const int qt = blockIdx.x;
    const int bh = blockIdx.y;
    const int b = bh / H_, h = bh - (bh / H_) * H_;
    const int tid = threadIdx.x;
    const int q  = tid >> 2;
    const int dg = (tid & 3) * 16;
    const int q0 = qt * 64;

    __shared__ float KS[64][68];
    __shared__ float Vs[64][68];
    __shared__ float rowm[64], rows[64], cfs[64];

    float4 qr[16];
    const float* qp = g_q + ((size_t)(b * S_ + q0 + q)) * D_ + h * HD_;
#pragma unroll
    for (int j = 0; j < 16; j++) qr[j] = *(const float4*)(qp + 4 * j);

    float acc[16];
#pragma unroll
    for (int j = 0; j < 16; j++) acc[j] = 0.f;
    if (tid < 64) { rowm[tid] = -1e30f; rows[tid] = 0.f; }

    for (int k0 = 0; k0 <= q0; k0 += 64) {
        {
            int r = tid >> 2, c = (tid & 3) * 16;
            const float* kp = g_k + ((size_t)(b * S_ + k0 + r)) * D_ + h * HD_ + c;
            const float* vp = g_v + ((size_t)(b * S_ + k0 + r)) * D_ + h * HD_ + c;
#pragma unroll
            for (int j = 0; j < 4; j++) {
                *(float4*)&KS[r][c + 4 * j] = *(const float4*)(kp + 4 * j);
                *(float4*)&Vs[r][c + 4 * j] = *(const float4*)(vp + 4 * j);
            }
        }
        __syncthreads();

        float sreg[16];
        {
            const int kb = (tid & 3) * 16;
#pragma unroll
            for (int j = 0; j < 16; j++) {
                int kk = kb + j;
                float d = 0.f;
#pragma unroll
                for (int t4 = 0; t4 < 16; t4++) {
                    float4 kv = *(const float4*)&KS[kk][4 * t4];
                    d += qr[t4].x * kv.x + qr[t4].y * kv.y +
                         qr[t4].z * kv.z + qr[t4].w * kv.w;
                }
                sreg[j] = (k0 + kk <= q0 + q) ? d * 0.125f : -1e30f;
            }
        }
        __syncthreads();

        {
            const int kb = (tid & 3) * 16;
#pragma unroll
            for (int j = 0; j < 16; j++) KS[q][kb + j] = sreg[j];
        }
        __syncthreads();

        if (tid < 64) {
            float mo = rowm[tid];
            float tm = mo;
#pragma unroll 8
            for (int kk = 0; kk < 64; kk++) tm = fmaxf(tm, KS[tid][kk]);
            float cf = expf(mo - tm);
            float ps = 0.f;
#pragma unroll 8
            for (int kk = 0; kk < 64; kk++) {
                float p = expf(KS[tid][kk] - tm);
                KS[tid][kk] = p;
                ps += p;
            }
            rowm[tid] = tm;
            rows[tid] = rows[tid] * cf + ps;
            cfs[tid] = cf;
        }
        __syncthreads();

        {
            float cf = cfs[q];
#pragma unroll
            for (int j = 0; j < 16; j++) acc[j] *= cf;
            for (int kk = 0; kk < 64; kk++) {
                float p = KS[q][kk];
#pragma unroll
                for (int j4 = 0; j4 < 4; j4++) {
                    float4 vv = *(const float4*)&Vs[kk][dg + 4 * j4];
                    acc[4 * j4 + 0] += p * vv.x;
                    acc[4 * j4 + 1] += p * vv.y;
                    acc[4 * j4 + 2] += p * vv.z;
                    acc[4 * j4 + 3] += p * vv.w;
                }
            }
        }
        __syncthreads();
    }

    float inv = 1.f / rows[q];
    size_t base = ((size_t)(b * S_ + q0 + q)) * D_ + h * HD_ + dg;
#pragma unroll
    for (int j2 = 0; j2 < 8; j2++) {
        float v0 = acc[2 * j2] * inv, v1 = acc[2 * j2 + 1] * inv;
        *(__half2*)(g_oh + base + 2 * j2) = __floats2half2_rn(v0, v1);
    }
}

// ---------------- sparse BCE correction ----------------
__global__ void corr_kernel(const int* __restrict__ y) {
    int s = blockIdx.x * blockDim.x + threadIdx.x;
    if (s >= S_) return;
    int tok[2][FCS_];
    for (int b = 0; b < 2; b++)
        for (int j = 0; j < FCS_; j++)
            tok[b][j] = y[b * YW_ + (FCS_ - 1) + ((s - (FCS_ - 1) + j + S_) & (S_ - 1))];
    double dsum = 0.0;
    for (int b = 0; b < 2; b++)
        for (int j = 0; j < FCS_; j++) {
            int v = tok[b][j];
            bool first = true;
            for (int b2 = 0; b2 <= b && first; b2++) {
                int jmax = (b2 == b) ? j : FCS_;
                for (int j2 = 0; j2 < jmax; j2++)
                    if (tok[b2][j2] == v) { first = false; break; }
            }
            if (!first) continue;
            int c0 = 0, c1 = 0;
            for (int j2 = 0; j2 < FCS_; j2++) {
                c0 += (tok[0][j2] == v);
                c1 += (tok[1][j2] == v);
            }
            float w = (c0 > 1 || c1 > 1) ? 1.5f : 1.0f;
            for (int b2 = 0; b2 < 2; b2++) {
                float cv = g_c[((size_t)(b2 * S_ + s)) * V_ + v];
                float t  = ((b2 == 0 ? c0 : c1) > 0) ? 1.f : 0.f;
                dsum += (double)((w - 1.f) * softplusf(cv) - w * t * cv);
            }
        }
    atomicAdd(&g_acc[1], dsum);
}

// ---------------- logits += exp-kernel context (ring-buffer window) ----
#define CTX_CHUNK 128
__global__ void ctx_scan_kernel(float* __restrict__ logits, const float* __restrict__ conv_w) {
    int v = blockIdx.x * blockDim.x + threadIdx.x;
    if (v >= V_) return;
    int b  = blockIdx.y;
    int s0 = blockIdx.z * CTX_CHUNK;
    float e = expf(-conv_w[0]);

    float pw[FCS_];
    pw[FCS_ - 1] = 1.f;
#pragma unroll
    for (int d = FCS_ - 1; d >= 1; --d) pw[d - 1] = pw[d] * e;

    float ring[FCS_];
#pragma unroll
    for (int j = 1; j <= FCS_; j++) {
        int sp = s0 - j;
        ring[(8 - j) & 7] = (sp >= 0) ? g_c[((size_t)(b * S_ + sp)) * V_ + v] : 0.f;
    }

    for (int t = 0; t < CTX_CHUNK / 8; t++) {
#pragma unroll
        for (int u = 0; u < 8; u++) {
            int s = s0 + 8 * t + u;
            size_t idx = ((size_t)(b * S_ + s)) * V_ + v;
            float ctx = 0.f;
#pragma unroll
            for (int d = 1; d <= FCS_; d++)
                ctx += pw[d - 1] * ring[(u - d) & 7];
            logits[idx] += ctx;
            ring[u] = g_c[idx];
        }
    }
}

// ---------------- NLL ----------------
__global__ void nll_kernel(const float* __restrict__ logits, const int* __restrict__ y) {
    int row = blockIdx.x;
    int b = row / S_, s = row - (row / S_) * S_;
    const float* lp = logits + (size_t)row * V_;
    __shared__ float red[256];
    float m = -1e30f;
    for (int v = threadIdx.x; v < V_; v += 256) m = fmaxf(m, lp[v]);
    red[threadIdx.x] = m; __syncthreads();
    for (int st = 128; st > 0; st >>= 1) {
        if (threadIdx.x < st) red[threadIdx.x] = fmaxf(red[threadIdx.x], red[threadIdx.x + st]);
        __syncthreads();
    }
    m = red[0];
    __syncthreads();
    float ssum = 0.f;
    for (int v = threadIdx.x; v < V_; v += 256) ssum += expf(lp[v] - m);
    red[threadIdx.x] = ssum; __syncthreads();
    for (int st = 128; st > 0; st >>= 1) {
        if (threadIdx.x < st) red[threadIdx.x] += red[threadIdx.x + st];
        __syncthreads();
    }
    if (threadIdx.x == 0) {
        int yt = y[b * YW_ + s];
        if (yt != -1) {
            float lse = m + logf(red[0]);
            atomicAdd(&g_acc[2], (double)(lse - lp[yt]));
            atomicAdd(&g_acc[3], 1.0);
        }
    }
}

__global__ void finalize_kernel(float* __restrict__ out) {
    double cnt = g_acc[3] < 1.0 ? 1.0 : g_acc[3];
    out[(size_t)NT_ * V_]     = (float)(g_acc[2] / cnt);
    out[(size_t)NT_ * V_ + 1] = (float)((g_acc[0] + g_acc[1]) / ((double)NT_ * (double)V_));
}

// ---------------- launcher ----------------
extern "C" void kernel_launch(void* const* d_in, const int* in_sizes, int n_in,
                              void* d_out, int out_size) {
    const int*   x      = (const int*)  d_in[0];
    const int*   y      = (const int*)  d_in[1];
    const float* emb    = (const float*)d_in[2];
    const float* wq     = (const float*)d_in[3];
    const float* wk     = (const float*)d_in[4];
    const float* wv     = (const float*)d_in[5];
    const float* wo     = (const float*)d_in[6];
    const float* w1     = (const float*)d_in[7];
    const float* w2     = (const float*)d_in[8];
    const float* w3     = (const float*)d_in[9];
    const float* attn_n = (const float*)d_in[10];
    const float* ffn_n  = (const float*)d_in[11];
    const float* out_n  = (const float*)d_in[12];
    const float* w_out  = (const float*)d_in[13];
    const float* w_ctx  = (const float*)d_in[14];
    const float* conv_w = (const float*)d_in[15];
    float* out = (float*)d_out;

    float *h_, *q_, *k_, *v_, *g1_, *c_;
    __half *ah_, *al_, *oh_, *uh_, *ul_;
    __half *wq_f, *wk_f, *wv_f, *wo_f, *w1_f, *w3_f, *w2_f, *wout_f, *wctx_f;
    cudaGetSymbolAddress((void**)&h_,  g_h);
    cudaGetSymbolAddress((void**)&q_,  g_q);
    cudaGetSymbolAddress((void**)&k_,  g_k);
    cudaGetSymbolAddress((void**)&v_,  g_v);
    cudaGetSymbolAddress((void**)&g1_, g_g1);
    cudaGetSymbolAddress((void**)&c_,  g_c);
    cudaGetSymbolAddress((void**)&ah_, g_ah);
    cudaGetSymbolAddress((void**)&al_, g_al);
    cudaGetSymbolAddress((void**)&oh_, g_oh);
    cudaGetSymbolAddress((void**)&uh_, g_uh);
    cudaGetSymbolAddress((void**)&ul_, g_ul);
    cudaGetSymbolAddress((void**)&wq_f, g_wq);
    cudaGetSymbolAddress((void**)&wk_f, g_wk);
    cudaGetSymbolAddress((void**)&wv_f, g_wv);
    cudaGetSymbolAddress((void**)&wo_f, g_wo);
    cudaGetSymbolAddress((void**)&w1_f, g_w1);
    cudaGetSymbolAddress((void**)&w3_f, g_w3);
    cudaGetSymbolAddress((void**)&w2_f, g_w2);
    cudaGetSymbolAddress((void**)&wout_f, g_wout);
    cudaGetSymbolAddress((void**)&wctx_f, g_wctx);

    zero_acc_kernel<<<1, 32>>>();
    embed_kernel<<<(NT_ * D_ + 255) / 256, 256>>>(x, emb);
    rope_table_kernel<<<(S_ * 32 + 255) / 256, 256>>>();

    // weight converts (fp32 -> fp16, whole tensors)
    {
        int nDD4 = L_ * D_ * D_ / 4;
        int nFD4 = L_ * F_ * D_ / 4;
        int nVD4 = V_ * D_ / 4;
        wconv_kernel<<<(nDD4 + 255) / 256, 256>>>(wq, wq_f, nDD4);
        wconv_kernel<<<(nDD4 + 255) / 256, 256>>>(wk, wk_f, nDD4);
        wconv_kernel<<<(nDD4 + 255) / 256, 256>>>(wv, wv_f, nDD4);
        wconv_kernel<<<(nDD4 + 255) / 256, 256>>>(wo, wo_f, nDD4);
        wconv_kernel<<<(nFD4 + 255) / 256, 256>>>(w1, w1_f, nFD4);
        wconv_kernel<<<(nFD4 + 255) / 256, 256>>>(w3, w3_f, nFD4);
        wconv_kernel<<<(nFD4 + 255) / 256, 256>>>(w2, w2_f, nFD4);
        wconv_kernel<<<(nVD4 + 255) / 256, 256>>>(w_out, wout_f, nVD4);
        wconv_kernel<<<(nVD4 + 255) / 256, 256>>>(w_ctx, wctx_f, nVD4);
    }

    dim3 gQKV(NT_ / 64, D_ / 64, 3);     // 16 x 12 x 3 (64x64 tiles)
    dim3 gDs (NT_ / 64, D_ / 64);        // 16 x 12
    dim3 gF  (NT_ / 128, F_ / 64);       // 8 x 32 (128x64 tiles)
    dim3 gHD (NT_ / 128, V_ / 128, 2);   // 8 x 250 x 2 (fused heads)

    for (int i = 0; i < L_; i++) {
        int offDD = i * D_ * D_;
        int offFD = i * F_ * D_;

        // attn path: plain fp16 (1 mma/k16)
        rmsnorm_kernel<1><<<NT_, 256>>>(h_, attn_n + i * D_, ah_, nullptr);
        gemm_qkv_f16<<<gQKV, 128>>>(ah_, offDD, q_, k_, v_, D_, D_);
        rope_apply_kernel<<<(B_ * S_ * H_ * 32 + 255) / 256, 256>>>();
        attn_flash<<<dim3(S_ / 64, B_ * H_), 256>>>();
        gemm_f16<64, 64, 2, 2, 1, 1><<<gDs, 128>>>(oh_, nullptr, wo_f + offDD,
                                                   h_, nullptr, nullptr, nullptr, D_, D_);

        // ffn path: A-split fp16 (2 mma/k16; only weights round)
        rmsnorm_kernel<2><<<NT_, 256>>>(h_, ffn_n + i * D_, ah_, al_);
        gemm_f16<128, 64, 2, 2, 2, 2><<<gF, 128>>>(ah_, al_, w1_f + offFD,
                                                   g1_, nullptr, nullptr, nullptr, F_, D_);
        gemm_f16<128, 64, 2, 2, 3, 2><<<gF, 128>>>(ah_, al_, w3_f + offFD,
                                                   nullptr, g1_, uh_, ul_, F_, D_);
        gemm_f16<64, 64, 2, 2, 1, 2><<<gDs, 128>>>(uh_, ul_, w2_f + offFD,
                                                   h_, nullptr, nullptr, nullptr, D_, F_);
    }

    // fused heads: plain fp16 (1 mma/k16), one launch, 500 CTAs
    rmsnorm_kernel<1><<<NT_, 256>>>(h_, out_n, ah_, nullptr);
    gemm_heads_f16<<<gHD, 256>>>(ah_, out, c_);

    corr_kernel<<<(S_ + 255) / 256, 256>>>(y);
    ctx_scan_kernel<<<dim3((V_ + 255) / 256, B_, S_ / CTX_CHUNK), 256>>>(out, conv_w);
    nll_kernel<<<NT_, 256>>>(out, y);
    finalize_kernel<<<1, 1>>>(out);
}

// round 13
// speedup vs baseline: 1.2354x; 1.0053x over previous
#include <cuda_runtime.h>
#include <cuda_fp16.h>
#include <math.h>
#include <stdint.h>

#define B_  2
#define S_  512
#define V_  32000
#define D_  768
#define F_  2048
#define L_  4
#define H_  12
#define HD_ 64
#define FCS_ 8
#define YW_ (S_ + FCS_ - 1)   /* 519 */
#define NT_ (B_ * S_)         /* 1024 rows */

// ---------------- static scratch (allocation-free rule) ----------------
__device__ float  g_h [NT_ * D_];
__device__ float  g_q [NT_ * D_];
__device__ float  g_k [NT_ * D_];
__device__ float  g_v [NT_ * D_];
__device__ float  g_g1[NT_ * F_];
__device__ float  g_c [NT_ * V_];          // context head logits c (131 MB)
__device__ float2 g_rope[S_ * 32];
__device__ double g_acc[4];                // [0]=softplus [1]=delta [2]=nll [3]=valid

// fp16 activations (hi + lo residual where needed)
__device__ __align__(16) __half g_ah[NT_ * D_], g_al[NT_ * D_];
__device__ __align__(16) __half g_oh[NT_ * D_];
__device__ __align__(16) __half g_uh[NT_ * F_], g_ul[NT_ * F_];

// fp16 weights (converted once per launch)
__device__ __align__(16) __half g_wq[L_*D_*D_];
__device__ __align__(16) __half g_wk[L_*D_*D_];
__device__ __align__(16) __half g_wv[L_*D_*D_];
__device__ __align__(16) __half g_wo[L_*D_*D_];
__device__ __align__(16) __half g_w1[L_*F_*D_];
__device__ __align__(16) __half g_w3[L_*F_*D_];
__device__ __align__(16) __half g_w2[L_*D_*F_];
__device__ __align__(16) __half g_wout[V_*D_];
__device__ __align__(16) __half g_wctx[V_*D_];

__device__ __forceinline__ float softplusf(float x) {
    if (x > 15.0f) return x;
    return log1pf(expf(x));
}

__device__ __forceinline__ void mma_f16(float& c0, float& c1, float& c2, float& c3,
                                        uint32_t a0, uint32_t a1, uint32_t a2, uint32_t a3,
                                        uint32_t b0, uint32_t b1) {
    asm volatile("mma.sync.aligned.m16n8k16.row.col.f32.f16.f16.f32 "
                 "{%0,%1,%2,%3}, {%4,%5,%6,%7}, {%8,%9}, {%0,%1,%2,%3};"
                 : "+f"(c0), "+f"(c1), "+f"(c2), "+f"(c3)
                 : "r"(a0), "r"(a1), "r"(a2), "r"(a3), "r"(b0), "r"(b1));
}

// ---------------- weight convert fp32 -> fp16 (MLP=4 grid-stride) ----------------
__global__ void wconv_kernel(const float* __restrict__ src, __half* __restrict__ dst, int n4) {
    const int stride = blockDim.x * gridDim.x;
    int i = blockIdx.x * blockDim.x + threadIdx.x;
    float4 v[4];
    int idx[4];
#pragma unroll
    for (int u = 0; u < 4; u++) {
        idx[u] = i + u * stride;
        if (idx[u] < n4) v[u] = ((const float4*)src)[idx[u]];
    }
#pragma unroll
    for (int u = 0; u < 4; u++) {
        if (idx[u] < n4) {
            ((__half2*)dst)[2 * idx[u]]     = __floats2half2_rn(v[u].x, v[u].y);
            ((__half2*)dst)[2 * idx[u] + 1] = __floats2half2_rn(v[u].z, v[u].w);
        }
    }
}

// ---------------- embedding gather (+ acc zero + rope table fold-in) ----------
__global__ void embed_kernel(const int* __restrict__ x, const float* __restrict__ emb) {
    int i = blockIdx.x * blockDim.x + threadIdx.x;
    if (i < 4) g_acc[i] = 0.0;
    if (i < S_ * 32) {
        int s = i / 32, p = i - (i / 32) * 32;
        float f   = expf((float)(2 * p) * (-logf(10000.0f) / (float)HD_));
        float ang = (float)s * f;
        double a  = (double)ang;
        g_rope[i] = make_float2((float)cos(a), (float)sin(a));
    }
    if (i >= NT_ * D_) return;
    int row = i / D_;
    int d   = i - row * D_;
    g_h[i] = emb[(size_t)x[row] * D_ + d];
}

// ---------------- rmsnorm (SPLIT: 1=fp16 hi only, 2=fp16 hi+lo) ----------------
template<int SPLIT>
__global__ void rmsnorm_kernel(const float* __restrict__ in, const float* __restrict__ w,
                               __half* __restrict__ oh, __half* __restrict__ ol) {
    int row = blockIdx.x;
    const float* ip = in + row * D_;
    __shared__ float red[256];
    float ss = 0.f;
    for (int d = threadIdx.x; d < D_; d += 256) { float v = ip[d]; ss += v * v; }
    red[threadIdx.x] = ss; __syncthreads();
    for (int st = 128; st > 0; st >>= 1) {
        if (threadIdx.x < st) red[threadIdx.x] += red[threadIdx.x + st];
        __syncthreads();
    }
    float rs = rsqrtf(red[0] / (float)D_ + 1e-5f);
    for (int d = threadIdx.x; d < D_; d += 256) {
        float v = ip[d] * rs * w[d];
        __half h = __float2half_rn(v);
        oh[row * D_ + d] = h;
        if (SPLIT == 2) ol[row * D_ + d] = __float2half_rn(v - __half2float(h));
    }
}

#define TLD 20   /* smem row stride (u32): fragment loads conflict-free */

// =======================================================================
//  fp16 NT-GEMM:  C[m,n] (op)= sum_k A[m,k]*W[n,k]
//  NI=1: A=hi only (1 mma/k16).  NI=2: A=hi+lo residual (2 mma/k16).
//  EPI: 0=store 1=add 2=silu 3=mulG->fp16 hi/lo 4=store+softplus 5=rope-store
// =======================================================================
template<int BM, int BN, int WM, int WN, int EPI, int NI>
__device__ __forceinline__ void gemm_f16_core(const __half* __restrict__ Ah,
                                              const __half* __restrict__ Al,
                                              const __half* __restrict__ Bw,
                                              float* __restrict__ C,
                                              const float* __restrict__ G,
                                              __half* __restrict__ Oh,
                                              __half* __restrict__ Ol,
                                              int N, int K, int bm, int bn) {
    constexpr int THREADS = WM * WN * 32;
    constexpr int WTM = BM / WM;
    constexpr int WTN = BN / WN;
    constexpr int MT  = WTM / 16;
    constexpr int NTT = WTN / 8;
    constexpr int RPP = THREADS / 2;
    constexpr int NLA = BM / RPP;
    constexpr int NLB = BN / RPP;

    __shared__ uint32_t As[2][BM][TLD];
    __shared__ uint32_t Bs[2][BN][TLD];
    __shared__ float sred[THREADS];

    const int tid  = threadIdx.x;
    const int lane = tid & 31;
    const int wid  = tid >> 5;
    const int wm   = wid / WN;
    const int wn   = wid % WN;

    const int lr = tid >> 1;
    const int ks = (tid & 1) * 8;   // element offset 0/8 in k16 chunk
    const int js = ks >> 1;         // u32 pair offset 0/4
    const __half* Agh = Ah + (size_t)(bm + lr) * K + ks;
    const __half* Agl = (NI == 2) ? Al + (size_t)(bm + lr) * K + ks : nullptr;
    const __half* Bg  = Bw + (size_t)(bn + lr) * K + ks;

    float acc[MT][NTT][4];
#pragma unroll
    for (int i = 0; i < MT; i++)
#pragma unroll
        for (int j = 0; j < NTT; j++)
#pragma unroll
            for (int q = 0; q < 4; q++) acc[i][j][q] = 0.f;

    uint4 pah[NLA], pal[NLA], pbh[NLB];

#pragma unroll
    for (int l = 0; l < NLA; l++) {
        pah[l] = *(const uint4*)(Agh + (size_t)l * RPP * K);
        if (NI == 2) pal[l] = *(const uint4*)(Agl + (size_t)l * RPP * K);
    }
#pragma unroll
    for (int l = 0; l < NLB; l++)
        pbh[l] = *(const uint4*)(Bg + (size_t)l * RPP * K);

    auto store_tiles = [&](int buf) {
#pragma unroll
        for (int l = 0; l < NLA; l++) {
            *(uint4*)&As[buf][lr + l * RPP][js] = pah[l];
            if (NI == 2) *(uint4*)&As[buf][lr + l * RPP][8 + js] = pal[l];
        }
#pragma unroll
        for (int l = 0; l < NLB; l++)
            *(uint4*)&Bs[buf][lr + l * RPP][js] = pbh[l];
    };

    store_tiles(0);
    __syncthreads();

    const int nk = K / 16;
    for (int kc = 0; kc < nk; kc++) {
        const int cur = kc & 1;
        if (kc + 1 < nk) {
            const int off = (kc + 1) * 16;
#pragma unroll
            for (int l = 0; l < NLA; l++) {
                pah[l] = *(const uint4*)(Agh + (size_t)l * RPP * K + off);
                if (NI == 2) pal[l] = *(const uint4*)(Agl + (size_t)l * RPP * K + off);
            }
#pragma unroll
            for (int l = 0; l < NLB; l++)
                pbh[l] = *(const uint4*)(Bg + (size_t)l * RPP * K + off);
        }

        {
            const int jq = lane & 3;
            uint32_t ah[MT][4], al[MT][4], bh[NTT][2];
#pragma unroll
            for (int mt = 0; mt < MT; mt++) {
                int row = wm * WTM + mt * 16 + (lane >> 2);
                ah[mt][0] = As[cur][row][jq];
                ah[mt][1] = As[cur][row + 8][jq];
                ah[mt][2] = As[cur][row][jq + 4];
                ah[mt][3] = As[cur][row + 8][jq + 4];
                if (NI == 2) {
                    al[mt][0] = As[cur][row][jq + 8];
                    al[mt][1] = As[cur][row + 8][jq + 8];
                    al[mt][2] = As[cur][row][jq + 12];
                    al[mt][3] = As[cur][row + 8][jq + 12];
                }
            }
#pragma unroll
            for (int nt = 0; nt < NTT; nt++) {
                int nr = wn * WTN + nt * 8 + (lane >> 2);
                bh[nt][0] = Bs[cur][nr][jq];
                bh[nt][1] = Bs[cur][nr][jq + 4];
            }
#pragma unroll
            for (int mt = 0; mt < MT; mt++)
#pragma unroll
                for (int nt = 0; nt < NTT; nt++) {
                    mma_f16(acc[mt][nt][0], acc[mt][nt][1], acc[mt][nt][2], acc[mt][nt][3],
                            ah[mt][0], ah[mt][1], ah[mt][2], ah[mt][3],
                            bh[nt][0], bh[nt][1]);
                    if (NI == 2)
                        mma_f16(acc[mt][nt][0], acc[mt][nt][1], acc[mt][nt][2], acc[mt][nt][3],
                                al[mt][0], al[mt][1], al[mt][2], al[mt][3],
                                bh[nt][0], bh[nt][1]);
                }
        }

        if (kc + 1 < nk) store_tiles(cur ^ 1);
        __syncthreads();
    }

    // ---------------- epilogue ----------------
    float spsum = 0.f;
#pragma unroll
    for (int mt = 0; mt < MT; mt++) {
        int row = bm + wm * WTM + mt * 16 + (lane >> 2);
#pragma unroll
        for (int nt = 0; nt < NTT; nt++) {
            int col = bn + wn * WTN + nt * 8 + (lane & 3) * 2;
            float* a4 = acc[mt][nt];
            size_t i0 = (size_t)row * N + col;
            size_t i1 = (size_t)(row + 8) * N + col;
            float2 r0 = make_float2(a4[0], a4[1]);
            float2 r1 = make_float2(a4[2], a4[3]);
            if (EPI == 1) {
                float2 o0 = *(const float2*)(C + i0);
                float2 o1 = *(const float2*)(C + i1);
                r0.x += o0.x; r0.y += o0.y;
                r1.x += o1.x; r1.y += o1.y;
            } else if (EPI == 2) {
                r0.x = r0.x / (1.f + expf(-r0.x));
                r0.y = r0.y / (1.f + expf(-r0.y));
                r1.x = r1.x / (1.f + expf(-r1.x));
                r1.y = r1.y / (1.f + expf(-r1.y));
            } else if (EPI == 3) {
                float2 g0 = *(const float2*)(G + i0);
                float2 g1v = *(const float2*)(G + i1);
                r0.x *= g0.x; r0.y *= g0.y;
                r1.x *= g1v.x; r1.y *= g1v.y;
            } else if (EPI == 4) {
                spsum += softplusf(r0.x) + softplusf(r0.y) +
                         softplusf(r1.x) + softplusf(r1.y);
            } else if (EPI == 5) {
                // fused RoPE: float2 = (xr, xi) pair; p = (col%64)/2, s = row%512
                int p = (col & 63) >> 1;
                {
                    float2 cs = g_rope[(row & (S_ - 1)) * 32 + p];
                    float xr = r0.x, xi = r0.y;
                    r0.x = xr * cs.x - xi * cs.y;
                    r0.y = xr * cs.y + xi * cs.x;
                }
                {
                    float2 cs = g_rope[((row + 8) & (S_ - 1)) * 32 + p];
                    float xr = r1.x, xi = r1.y;
                    r1.x = xr * cs.x - xi * cs.y;
                    r1.y = xr * cs.y + xi * cs.x;
                }
            }
            if (EPI == 3) {
                __half2 h0 = __floats2half2_rn(r0.x, r0.y);
                __half2 h1 = __floats2half2_rn(r1.x, r1.y);
                __half2 l0 = __floats2half2_rn(r0.x - __half2float(__low2half(h0)),
                                               r0.y - __half2float(__high2half(h0)));
                __half2 l1 = __floats2half2_rn(r1.x - __half2float(__low2half(h1)),
                                               r1.y - __half2float(__high2half(h1)));
                *(__half2*)(Oh + i0) = h0;
                *(__half2*)(Oh + i1) = h1;
                *(__half2*)(Ol + i0) = l0;
                *(__half2*)(Ol + i1) = l1;
            } else {
                *(float2*)(C + i0) = r0;
                *(float2*)(C + i1) = r1;
            }
        }
    }
    if (EPI == 4) {
        sred[tid] = spsum; __syncthreads();
        for (int st = THREADS / 2; st > 0; st >>= 1) {
            if (tid < st) sred[tid] += sred[tid + st];
            __syncthreads();
        }
        if (tid == 0) atomicAdd(&g_acc[0], (double)sred[0]);
    }
}

template<int BM, int BN, int WM, int WN, int EPI, int NI>
__global__ __launch_bounds__(WM * WN * 32)
void gemm_f16(const __half* __restrict__ Ah, const __half* __restrict__ Al,
              const __half* __restrict__ Bw,
              float* __restrict__ C, const float* __restrict__ G,
              __half* __restrict__ Oh, __half* __restrict__ Ol, int N, int K) {
    gemm_f16_core<BM, BN, WM, WN, EPI, NI>(Ah, Al, Bw, C, G, Oh, Ol, N, K,
                                           blockIdx.x * BM, blockIdx.y * BN);
}

// fused q/k/v (blockIdx.z selects weight/output); q,k get fused RoPE (EPI5)
__global__ __launch_bounds__(128)
void gemm_qkv_f16(const __half* __restrict__ Ah, int layer_off,
                  float* __restrict__ C0, float* __restrict__ C1, float* __restrict__ C2) {
    if (blockIdx.z == 0)
        gemm_f16_core<64, 64, 2, 2, 5, 1>(Ah, nullptr, g_wq + layer_off, C0, nullptr,
                                          nullptr, nullptr, D_, D_,
                                          blockIdx.x * 64, blockIdx.y * 64);
    else if (blockIdx.z == 1)
        gemm_f16_core<64, 64, 2, 2, 5, 1>(Ah, nullptr, g_wk + layer_off, C1, nullptr,
                                          nullptr, nullptr, D_, D_,
                                          blockIdx.x * 64, blockIdx.y * 64);
    else
        gemm_f16_core<64, 64, 2, 2, 0, 1>(Ah, nullptr, g_wv + layer_off, C2, nullptr,
                                          nullptr, nullptr, D_, D_,
                                          blockIdx.x * 64, blockIdx.y * 64);
}

// fused heads: z=0 -> logits (EPI0, w_out); z=1 -> c + softplus (EPI4, w_ctx)
__global__ __launch_bounds__(256)
void gemm_heads_f16(const __half* __restrict__ Ah,
                    float* __restrict__ Cout, float* __restrict__ Cc) {
    if (blockIdx.z == 0)
        gemm_f16_core<128, 128, 2, 4, 0, 1>(Ah, nullptr, g_wout, Cout, nullptr,
                                            nullptr, nullptr, V_, D_,
                                            blockIdx.x * 128, blockIdx.y * 128);
    else
        gemm_f16_core<128, 128, 2, 4, 4, 1>(Ah, nullptr, g_wctx, Cc, nullptr,
                                            nullptr, nullptr, V_, D_,
                                            blockIdx.x * 128, blockIdx.y * 128);
}

// ---------------- flash-style attention (writes o as fp16 hi) ----------------
__global__ __launch_bounds__(256)
void attn_flash() {
    const int qt = blockIdx.x;
    const int bh = blockIdx.y;
    const int b = bh / H_, h = bh - (bh / H_) * H_;
    const int tid = threadIdx.x;
    const int q  = tid >> 2;
    const int dg = (tid & 3) * 16;
    const int q0 = qt * 64;

    __shared__ float KS[64][68];
    __shared__ float Vs[64][68];
    __shared__ float rowm[64], rows[64], cfs[64];

    float4 qr[16];
    const float* qp = g_q + ((size_t)(b * S_ + q0 + q)) * D_ + h * HD_;
#pragma unroll
    for (int j = 0; j < 16; j++) qr[j] = *(const float4*)(qp + 4 * j);

    float acc[16];
#pragma unroll
    for (int j = 0; j < 16; j++) acc[j] = 0.f;
    if (tid < 64) { rowm[tid] = -1e30f; rows[tid] = 0.f; }

    for (int k0 = 0; k0 <= q0; k0 += 64) {
        {
            int r = tid >> 2, c = (tid & 3) * 16;
            const float* kp = g_k + ((size_t)(b * S_ + k0 + r)) * D_ + h * HD_ + c;
            const float* vp = g_v + ((size_t)(b * S_ + k0 + r)) * D_ + h * HD_ + c;
#pragma unroll
            for (int j = 0; j < 4; j++) {
                *(float4*)&KS[r][c + 4 * j] = *(const float4*)(kp + 4 * j);
                *(float4*)&Vs[r][c + 4 * j] = *(const float4*)(vp + 4 * j);
            }
        }
        __syncthreads();

        float sreg[16];
        {
            const int kb = (tid & 3) * 16;
#pragma unroll
            for (int j = 0; j < 16; j++) {
                int kk = kb + j;
                float d = 0.f;
#pragma unroll
                for (int t4 = 0; t4 < 16; t4++) {
                    float4 kv = *(const float4*)&KS[kk][4 * t4];
                    d += qr[t4].x * kv.x + qr[t4].y * kv.y +
                         qr[t4].z * kv.z + qr[t4].w * kv.w;
                }
                sreg[j] = (k0 + kk <= q0 + q) ? d * 0.125f : -1e30f;
            }
        }
        __syncthreads();

        {
            const int kb = (tid & 3) * 16;
#pragma unroll
            for (int j = 0; j < 16; j++) KS[q][kb + j] = sreg[j];
        }
        __syncthreads();

        if (tid < 64) {
            float mo = rowm[tid];
            float tm = mo;
#pragma unroll 8
            for (int kk = 0; kk < 64; kk++) tm = fmaxf(tm, KS[tid][kk]);
            float cf = expf(mo - tm);
            float ps = 0.f;
#pragma unroll 8
            for (int kk = 0; kk < 64; kk++) {
                float p = expf(KS[tid][kk] - tm);
                KS[tid][kk] = p;
                ps += p;
            }
            rowm[tid] = tm;
            rows[tid] = rows[tid] * cf + ps;
            cfs[tid] = cf;
        }
        __syncthreads();

        {
            float cf = cfs[q];
#pragma unroll
            for (int j = 0; j < 16; j++) acc[j] *= cf;
            for (int kk = 0; kk < 64; kk++) {
                float p = KS[q][kk];
#pragma unroll
                for (int j4 = 0; j4 < 4; j4++) {
                    float4 vv = *(const float4*)&Vs[kk][dg + 4 * j4];
                    acc[4 * j4 + 0] += p * vv.x;
                    acc[4 * j4 + 1] += p * vv.y;
                    acc[4 * j4 + 2] += p * vv.z;
                    acc[4 * j4 + 3] += p * vv.w;
                }
            }
        }
        __syncthreads();
    }

    float inv = 1.f / rows[q];
    size_t base = ((size_t)(b * S_ + q0 + q)) * D_ + h * HD_ + dg;
#pragma unroll
    for (int j2 = 0; j2 < 8; j2++) {
        float v0 = acc[2 * j2] * inv, v1 = acc[2 * j2 + 1] * inv;
        *(__half2*)(g_oh + base + 2 * j2) = __floats2half2_rn(v0, v1);
    }
}

// ---------------- sparse BCE correction ----------------
__global__ void corr_kernel(const int* __restrict__ y) {
    int s = blockIdx.x * blockDim.x + threadIdx.x;
    if (s >= S_) return;
    int tok[2][FCS_];
    for (int b = 0; b < 2; b++)
        for (int j = 0; j < FCS_; j++)
            tok[b][j] = y[b * YW_ + (FCS_ - 1) + ((s - (FCS_ - 1) + j + S_) & (S_ - 1))];
    double dsum = 0.0;
    for (int b = 0; b < 2; b++)
        for (int j = 0; j < FCS_; j++) {
            int v = tok[b][j];
            bool first = true;
            for (int b2 = 0; b2 <= b && first; b2++) {
                int jmax = (b2 == b) ? j : FCS_;
                for (int j2 = 0; j2 < jmax; j2++)
                    if (tok[b2][j2] == v) { first = false; break; }
            }
            if (!first) continue;
            int c0 = 0, c1 = 0;
            for (int j2 = 0; j2 < FCS_; j2++) {
                c0 += (tok[0][j2] == v);
                c1 += (tok[1][j2] == v);
            }
            float w = (c0 > 1 || c1 > 1) ? 1.5f : 1.0f;
            for (int b2 = 0; b2 < 2; b2++) {
                float cv = g_c[((size_t)(b2 * S_ + s)) * V_ + v];
                float t  = ((b2 == 0 ? c0 : c1) > 0) ? 1.f : 0.f;
                dsum += (double)((w - 1.f) * softplusf(cv) - w * t * cv);
            }
        }
    atomicAdd(&g_acc[1], dsum);
}

// ---------------- logits += exp-kernel context (ring-buffer window) ----
#define CTX_CHUNK 128
__global__ void ctx_scan_kernel(float* __restrict__ logits, const float* __restrict__ conv_w) {
    int v = blockIdx.x * blockDim.x + threadIdx.x;
    if (v >= V_) return;
    int b  = blockIdx.y;
    int s0 = blockIdx.z * CTX_CHUNK;
    float e = expf(-conv_w[0]);

    float pw[FCS_];
    pw[FCS_ - 1] = 1.f;
#pragma unroll
    for (int d = FCS_ - 1; d >= 1; --d) pw[d - 1] = pw[d] * e;

    float ring[FCS_];
#pragma unroll
    for (int j = 1; j <= FCS_; j++) {
        int sp = s0 - j;
        ring[(8 - j) & 7] = (sp >= 0) ? g_c[((size_t)(b * S_ + sp)) * V_ + v] : 0.f;
    }

    for (int t = 0; t < CTX_CHUNK / 8; t++) {
#pragma unroll
        for (int u = 0; u < 8; u++) {
            int s = s0 + 8 * t + u;
            size_t idx = ((size_t)(b * S_ + s)) * V_ + v;
            float ctx = 0.f;
#pragma unroll
            for (int d = 1; d <= FCS_; d++)
                ctx += pw[d - 1] * ring[(u - d) & 7];
            logits[idx] += ctx;
            ring[u] = g_c[idx];
        }
    }
}

// ---------------- NLL (one-pass online logsumexp) ----------------
__global__ void nll_kernel(const float* __restrict__ logits, const int* __restrict__ y) {
    int row = blockIdx.x;
    int b = row / S_, s = row - (row / S_) * S_;
    const float* lp = logits + (size_t)row * V_;
    __shared__ float rm[256], rs[256];
    float m = -1e30f, ssum = 0.f;
    for (int v = threadIdx.x; v < V_; v += 256) {
        float xv = lp[v];
        if (xv > m) { ssum = ssum * expf(m - xv) + 1.f; m = xv; }
        else        { ssum += expf(xv - m); }
    }
    rm[threadIdx.x] = m; rs[threadIdx.x] = ssum; __syncthreads();
    for (int st = 128; st > 0; st >>= 1) {
        if (threadIdx.x < st) {
            float m2 = rm[threadIdx.x + st], s2 = rs[threadIdx.x + st];
            float mm = fmaxf(rm[threadIdx.x], m2);
            rs[threadIdx.x] = rs[threadIdx.x] * expf(rm[threadIdx.x] - mm) +
                              s2 * expf(m2 - mm);
            rm[threadIdx.x] = mm;
        }
        __syncthreads();
    }
    if (threadIdx.x == 0) {
        int yt = y[b * YW_ + s];
        if (yt != -1) {
            float lse = rm[0] + logf(rs[0]);
            atomicAdd(&g_acc[2], (double)(lse - lp[yt]));
            atomicAdd(&g_acc[3], 1.0);
        }
    }
}

__global__ void finalize_kernel(float* __restrict__ out) {
    double cnt = g_acc[3] < 1.0 ? 1.0 : g_acc[3];
    out[(size_t)NT_ * V_]     = (float)(g_acc[2] / cnt);
    out[(size_t)NT_ * V_ + 1] = (float)((g_acc[0] + g_acc[1]) / ((double)NT_ * (double)V_));
}

// ---------------- launcher ----------------
extern "C" void kernel_launch(void* const* d_in, const int* in_sizes, int n_in,
                              void* d_out, int out_size) {
    const int*   x      = (const int*)  d_in[0];
    const int*   y      = (const int*)  d_in[1];
    const float* emb    = (const float*)d_in[2];
    const float* wq     = (const float*)d_in[3];
    const float* wk     = (const float*)d_in[4];
    const float* wv     = (const float*)d_in[5];
    const float* wo     = (const float*)d_in[6];
    const float* w1     = (const float*)d_in[7];
    const float* w2     = (const float*)d_in[8];
    const float* w3     = (const float*)d_in[9];
    const float* attn_n = (const float*)d_in[10];
    const float* ffn_n  = (const float*)d_in[11];
    const float* out_n  = (const float*)d_in[12];
    const float* w_out  = (const float*)d_in[13];
    const float* w_ctx  = (const float*)d_in[14];
    const float* conv_w = (const float*)d_in[15];
    float* out = (float*)d_out;

    float *h_, *q_, *k_, *v_, *g1_, *c_;
    __half *ah_, *al_, *oh_, *uh_, *ul_;
    __half *wq_f, *wk_f, *wv_f, *wo_f, *w1_f, *w3_f, *w2_f, *wout_f, *wctx_f;
    cudaGetSymbolAddress((void**)&h_,  g_h);
    cudaGetSymbolAddress((void**)&q_,  g_q);
    cudaGetSymbolAddress((void**)&k_,  g_k);
    cudaGetSymbolAddress((void**)&v_,  g_v);
    cudaGetSymbolAddress((void**)&g1_, g_g1);
    cudaGetSymbolAddress((void**)&c_,  g_c);
    cudaGetSymbolAddress((void**)&ah_, g_ah);
    cudaGetSymbolAddress((void**)&al_, g_al);
    cudaGetSymbolAddress((void**)&oh_, g_oh);
    cudaGetSymbolAddress((void**)&uh_, g_uh);
    cudaGetSymbolAddress((void**)&ul_, g_ul);
    cudaGetSymbolAddress((void**)&wq_f, g_wq);
    cudaGetSymbolAddress((void**)&wk_f, g_wk);
    cudaGetSymbolAddress((void**)&wv_f, g_wv);
    cudaGetSymbolAddress((void**)&wo_f, g_wo);
    cudaGetSymbolAddress((void**)&w1_f, g_w1);
    cudaGetSymbolAddress((void**)&w3_f, g_w3);
    cudaGetSymbolAddress((void**)&w2_f, g_w2);
    cudaGetSymbolAddress((void**)&wout_f, g_wout);
    cudaGetSymbolAddress((void**)&wctx_f, g_wctx);

    embed_kernel<<<(NT_ * D_ + 255) / 256, 256>>>(x, emb);

    // weight converts (fp32 -> fp16, MLP=4)
    {
        int nDD4 = L_ * D_ * D_ / 4;
        int nFD4 = L_ * F_ * D_ / 4;
        int nVD4 = V_ * D_ / 4;
        int gDD = (nDD4 + 1023) / 1024, gFD = (nFD4 + 1023) / 1024, gVD = (nVD4 + 1023) / 1024;
        wconv_kernel<<<gDD, 256>>>(wq, wq_f, nDD4);
        wconv_kernel<<<gDD, 256>>>(wk, wk_f, nDD4);
        wconv_kernel<<<gDD, 256>>>(wv, wv_f, nDD4);
        wconv_kernel<<<gDD, 256>>>(wo, wo_f, nDD4);
        wconv_kernel<<<gFD, 256>>>(w1, w1_f, nFD4);
        wconv_kernel<<<gFD, 256>>>(w3, w3_f, nFD4);
        wconv_kernel<<<gFD, 256>>>(w2, w2_f, nFD4);
        wconv_kernel<<<gVD, 256>>>(w_out, wout_f, nVD4);
        wconv_kernel<<<gVD, 256>>>(w_ctx, wctx_f, nVD4);
    }

    dim3 gQKV(NT_ / 64, D_ / 64, 3);     // 16 x 12 x 3 (64x64 tiles)
    dim3 gDs (NT_ / 64, D_ / 64);        // 16 x 12
    dim3 gF  (NT_ / 128, F_ / 64);       // 8 x 32 (128x64 tiles)
    dim3 gHD (NT_ / 128, V_ / 128, 2);   // 8 x 250 x 2 (fused heads)

    for (int i = 0; i < L_; i++) {
        int offDD = i * D_ * D_;
        int offFD = i * F_ * D_;

        // attn path: plain fp16 (1 mma/k16), rope fused into q/k epilogues
        rmsnorm_kernel<1><<<NT_, 256>>>(h_, attn_n + i * D_, ah_, nullptr);
        gemm_qkv_f16<<<gQKV, 128>>>(ah_, offDD, q_, k_, v_);
        attn_flash<<<dim3(S_ / 64, B_ * H_), 256>>>();
        gemm_f16<64, 64, 2, 2, 1, 1><<<gDs, 128>>>(oh_, nullptr, wo_f + offDD,
                                                   h_, nullptr, nullptr, nullptr, D_, D_);

        // ffn path: A-split fp16 (2 mma/k16; only weights round)
        rmsnorm_kernel<2><<<NT_, 256>>>(h_, ffn_n + i * D_, ah_, al_);
        gemm_f16<128, 64, 2, 2, 2, 2><<<gF, 128>>>(ah_, al_, w1_f + offFD,
                                                   g1_, nullptr, nullptr, nullptr, F_, D_);
        gemm_f16<128, 64, 2, 2, 3, 2><<<gF, 128>>>(ah_, al_, w3_f + offFD,
                                                   nullptr, g1_, uh_, ul_, F_, D_);
        gemm_f16<64, 64, 2, 2, 1, 2><<<gDs, 128>>>(uh_, ul_, w2_f + offFD,
                                                   h_, nullptr, nullptr, nullptr, D_, F_);
    }

    // fused heads: plain fp16 (1 mma/k16), one launch, 500 CTAs
    rmsnorm_kernel<1><<<NT_, 256>>>(h_, out_n, ah_, nullptr);
    gemm_heads_f16<<<gHD, 256>>>(ah_, out, c_);

    corr_kernel<<<(S_ + 255) / 256, 256>>>(y);
    ctx_scan_kernel<<<dim3((V_ + 255) / 256, B_, S_ / CTX_CHUNK), 256>>>(out, conv_w);
    nll_kernel<<<NT_, 256>>>(out, y);
    finalize_kernel<<<1, 1>>>(out);
}